// round 9
// baseline (speedup 1.0000x reference)
#include <cuda_runtime.h>
#include <cuda_bf16.h>
#include <stdint.h>
#include <math.h>

#define MAXN 100000
#define MAXE 3200000

// ---------------- scratch (static device globals) ---------------------------
__device__ int          g_cursor[MAXN];
__device__ int          g_rowptr[MAXN + 1];
__device__ int          g_col[MAXE];
__device__ int          g_bsum[256];
__device__ float        g_z[4][MAXN * 64];     // fp32 master copies z0..z3
__device__ unsigned int g_zh[4][MAXN * 32];    // bf16x2 gather copies
__device__ float        g_u[MAXN * 64];
__device__ float        g_stats[256];          // sum | sumsq | scale | shift

__device__ __forceinline__ float lrelu(float x) { return x >= 0.f ? x : 0.01f * x; }

__device__ __forceinline__ unsigned int pack_bf16x2(float2 v) {
    __nv_bfloat162 b = __float22bfloat162_rn(v);
    return *(unsigned int*)&b;
}
__device__ __forceinline__ float bf_lo(unsigned int w) { return __int_as_float((int)(w << 16)); }
__device__ __forceinline__ float bf_hi(unsigned int w) { return __int_as_float((int)(w & 0xffff0000u)); }

// ---------------- CSR build --------------------------------------------------
__global__ void k_zero_deg(int n) {
    int i = blockIdx.x * blockDim.x + threadIdx.x;
    if (i < n) g_cursor[i] = 0;
}

__global__ void k_hist4(const int* __restrict__ dst, int e4, int e) {
    int stride = gridDim.x * blockDim.x;
    int t0 = blockIdx.x * blockDim.x + threadIdx.x;
    const int4* d4 = (const int4*)dst;
    for (int i = t0; i < e4; i += stride) {
        int4 d = d4[i];
        atomicAdd(&g_cursor[d.x], 1);
        atomicAdd(&g_cursor[d.y], 1);
        atomicAdd(&g_cursor[d.z], 1);
        atomicAdd(&g_cursor[d.w], 1);
    }
    for (int i = e4 * 4 + t0; i < e; i += stride)
        atomicAdd(&g_cursor[dst[i]], 1);
}

__global__ void k_scan1(int n) {
    __shared__ int wsum[32];
    int tid = threadIdx.x, lane = tid & 31, w = tid >> 5;
    int i = blockIdx.x * 1024 + tid;
    int v = (i < n) ? g_cursor[i] : 0;
    int x = v;
    #pragma unroll
    for (int off = 1; off < 32; off <<= 1) {
        int t = __shfl_up_sync(0xffffffffu, x, off);
        if (lane >= off) x += t;
    }
    if (lane == 31) wsum[w] = x;
    __syncthreads();
    if (w == 0) {
        int s = wsum[lane];
        #pragma unroll
        for (int off = 1; off < 32; off <<= 1) {
            int t = __shfl_up_sync(0xffffffffu, s, off);
            if (lane >= off) s += t;
        }
        wsum[lane] = s;
    }
    __syncthreads();
    int incl = x + (w > 0 ? wsum[w - 1] : 0);
    if (i < n) g_rowptr[i] = incl - v;
    if (tid == 1023) g_bsum[blockIdx.x] = incl;
}

__global__ void k_scan2(int nb) {
    __shared__ int ws[4];
    int tid = threadIdx.x, lane = tid & 31, w = tid >> 5;
    int v = (tid < nb) ? g_bsum[tid] : 0;
    int x = v;
    #pragma unroll
    for (int off = 1; off < 32; off <<= 1) {
        int t = __shfl_up_sync(0xffffffffu, x, off);
        if (lane >= off) x += t;
    }
    if (lane == 31) ws[w] = x;
    __syncthreads();
    if (tid == 0) {
        int c = 0;
        #pragma unroll
        for (int k = 0; k < 4; k++) { int t = ws[k]; ws[k] = c; c += t; }
    }
    __syncthreads();
    if (tid < nb) g_bsum[tid] = x - v + ws[w];
}

__global__ void k_scan3(int n, int e) {
    int i = blockIdx.x * 1024 + threadIdx.x;
    if (i < n) {
        int v = g_rowptr[i] + g_bsum[blockIdx.x];
        g_rowptr[i] = v;
        g_cursor[i] = v;
    }
    if (i == 0) g_rowptr[n] = e;
}

__global__ void k_fill4(const int* __restrict__ src, const int* __restrict__ dst, int e4, int e) {
    int stride = gridDim.x * blockDim.x;
    int t0 = blockIdx.x * blockDim.x + threadIdx.x;
    const int4* s4 = (const int4*)src;
    const int4* d4 = (const int4*)dst;
    for (int i = t0; i < e4; i += stride) {
        int4 d = d4[i];
        int4 s = s4[i];
        int p0 = atomicAdd(&g_cursor[d.x], 1);
        int p1 = atomicAdd(&g_cursor[d.y], 1);
        int p2 = atomicAdd(&g_cursor[d.z], 1);
        int p3 = atomicAdd(&g_cursor[d.w], 1);
        g_col[p0] = s.x; g_col[p1] = s.y; g_col[p2] = s.z; g_col[p3] = s.w;
    }
    for (int i = e4 * 4 + t0; i < e; i += stride) {
        int p = atomicAdd(&g_cursor[dst[i]], 1);
        g_col[p] = src[i];
    }
}

__global__ void k_hist(const int* __restrict__ dst, int e) {
    int stride = gridDim.x * blockDim.x;
    for (int i = blockIdx.x * blockDim.x + threadIdx.x; i < e; i += stride)
        atomicAdd(&g_cursor[dst[i]], 1);
}
__global__ void k_fill(const int* __restrict__ src, const int* __restrict__ dst, int e) {
    int stride = gridDim.x * blockDim.x;
    for (int i = blockIdx.x * blockDim.x + threadIdx.x; i < e; i += stride) {
        int p = atomicAdd(&g_cursor[dst[i]], 1);
        g_col[p] = src[i];
    }
}

// ---------------- embedding lookup (also zeroes stats) -----------------------
__global__ void k_embed(const int* __restrict__ deg, const float* __restrict__ emb, int n) {
    if (blockIdx.x == 0 && threadIdx.x < 128) g_stats[threadIdx.x] = 0.f;
    int i = blockIdx.x * blockDim.x + threadIdx.x;
    if (i >= n * 32) return;
    int node = i >> 5, j = i & 31;
    float2 v = ((const float2*)emb)[deg[node] * 32 + j];
    ((float2*)g_z[0])[i] = v;
    g_zh[0][i] = pack_bf16x2(v);
}

// ---------------- fused GIN layer: interleaved gather + dual GEMVs ------------
__global__ void __launch_bounds__(256) k_layer(
    const float* __restrict__ W1, const float* __restrict__ b1,
    const float* __restrict__ W2, const float* __restrict__ b2,
    const float* __restrict__ epsArr, int l, int n)
{
    __shared__ float4 sW1q[32][32];
    __shared__ float4 sW2q[32][32];
    __shared__ float2 sb1[32];
    __shared__ float2 sb2[32];
    __shared__ float4 sm4[8][2][16];
    __shared__ float4 sh4[8][2][16];
    __shared__ float  bstat[128];

    int tid = threadIdx.x;
    {
        const float2* w1v = (const float2*)(W1 + l * 4096);
        const float2* w2v = (const float2*)(W2 + l * 4096);
        for (int i = tid; i < 1024; i += 256) {
            int k2 = i >> 5, c = i & 31;
            float2 a = w1v[(2 * k2) * 32 + c];
            float2 b = w1v[(2 * k2 + 1) * 32 + c];
            sW1q[k2][c] = make_float4(a.x, a.y, b.x, b.y);
            float2 a2 = w2v[(2 * k2) * 32 + c];
            float2 b2v = w2v[(2 * k2 + 1) * 32 + c];
            sW2q[k2][c] = make_float4(a2.x, a2.y, b2v.x, b2v.y);
        }
        if (tid < 32) {
            sb1[tid] = ((const float2*)(b1 + l * 64))[tid];
            sb2[tid] = ((const float2*)(b2 + l * 64))[tid];
        }
        if (tid < 128) bstat[tid] = 0.f;
    }
    __syncthreads();

    float ep = 1.0f + epsArr[l];
    const float2*       __restrict__ x2 = (const float2*)g_z[l];
    const unsigned int* __restrict__ xh = g_zh[l];
    float2* o2 = (float2*)g_z[l + 1];
    int w = tid >> 5, lane = tid & 31;
    float ssx = 0.f, ssy = 0.f, sqx = 0.f, sqy = 0.f;
    int gw = (blockIdx.x * 256 + tid) >> 5;
    int nw = (gridDim.x * 256) >> 5;

    for (int base = gw * 2; base < n; base += nw * 2) {
        int nA = base, nB = base + 1;
        bool hasB = (nB < n);

        // ------- interleaved dual-node gather (MLP = 8) -------
        int bA = g_rowptr[nA], reA = g_rowptr[nA + 1];
        int bB = hasB ? g_rowptr[nB] : 0, reB = hasB ? g_rowptr[nB + 1] : 0;
        float2 xvA = x2[nA * 32 + lane];
        float2 xvB = hasB ? x2[nB * 32 + lane] : make_float2(0.f, 0.f);
        float aA0x = ep * xvA.x, aA0y = ep * xvA.y, aA1x = 0.f, aA1y = 0.f;
        float aB0x = ep * xvB.x, aB0y = ep * xvB.y, aB1x = 0.f, aB1y = 0.f;

        while (bA + 32 <= reA && bB + 32 <= reB) {
            int jA = g_col[bA + lane];
            int jB = g_col[bB + lane];
            #pragma unroll
            for (int t = 0; t < 32; t += 2) {
                int a0 = __shfl_sync(0xffffffffu, jA, t);
                int a1 = __shfl_sync(0xffffffffu, jA, t + 1);
                int c0 = __shfl_sync(0xffffffffu, jB, t);
                int c1 = __shfl_sync(0xffffffffu, jB, t + 1);
                unsigned int wA0 = xh[a0 * 32 + lane];
                unsigned int wA1 = xh[a1 * 32 + lane];
                unsigned int wB0 = xh[c0 * 32 + lane];
                unsigned int wB1 = xh[c1 * 32 + lane];
                aA0x += bf_lo(wA0); aA0y += bf_hi(wA0);
                aA1x += bf_lo(wA1); aA1y += bf_hi(wA1);
                aB0x += bf_lo(wB0); aB0y += bf_hi(wB0);
                aB1x += bf_lo(wB1); aB1y += bf_hi(wB1);
            }
            bA += 32; bB += 32;
        }
        while (bA + 32 <= reA) {
            int jA = g_col[bA + lane];
            #pragma unroll
            for (int t = 0; t < 32; t += 4) {
                int a0 = __shfl_sync(0xffffffffu, jA, t);
                int a1 = __shfl_sync(0xffffffffu, jA, t + 1);
                int a2 = __shfl_sync(0xffffffffu, jA, t + 2);
                int a3 = __shfl_sync(0xffffffffu, jA, t + 3);
                unsigned int w0 = xh[a0 * 32 + lane];
                unsigned int w1 = xh[a1 * 32 + lane];
                unsigned int w2 = xh[a2 * 32 + lane];
                unsigned int w3 = xh[a3 * 32 + lane];
                aA0x += bf_lo(w0); aA0y += bf_hi(w0);
                aA1x += bf_lo(w1); aA1y += bf_hi(w1);
                aA0x += bf_lo(w2); aA0y += bf_hi(w2);
                aA1x += bf_lo(w3); aA1y += bf_hi(w3);
            }
            bA += 32;
        }
        while (bB + 32 <= reB) {
            int jB = g_col[bB + lane];
            #pragma unroll
            for (int t = 0; t < 32; t += 4) {
                int a0 = __shfl_sync(0xffffffffu, jB, t);
                int a1 = __shfl_sync(0xffffffffu, jB, t + 1);
                int a2 = __shfl_sync(0xffffffffu, jB, t + 2);
                int a3 = __shfl_sync(0xffffffffu, jB, t + 3);
                unsigned int w0 = xh[a0 * 32 + lane];
                unsigned int w1 = xh[a1 * 32 + lane];
                unsigned int w2 = xh[a2 * 32 + lane];
                unsigned int w3 = xh[a3 * 32 + lane];
                aB0x += bf_lo(w0); aB0y += bf_hi(w0);
                aB1x += bf_lo(w1); aB1y += bf_hi(w1);
                aB0x += bf_lo(w2); aB0y += bf_hi(w2);
                aB1x += bf_lo(w3); aB1y += bf_hi(w3);
            }
            bB += 32;
        }
        {   // interleaved tails (<32 each)
            int remA = reA - bA, remB = reB - bB;
            int jA = (lane < remA) ? g_col[bA + lane] : 0;
            int jB = (lane < remB) ? g_col[bB + lane] : 0;
            int rem = remA > remB ? remA : remB;
            for (int t = 0; t < rem; t++) {
                int ja = __shfl_sync(0xffffffffu, jA, t);
                int jb = __shfl_sync(0xffffffffu, jB, t);
                if (t < remA) {
                    unsigned int wv = xh[ja * 32 + lane];
                    aA0x += bf_lo(wv); aA0y += bf_hi(wv);
                }
                if (t < remB) {
                    unsigned int wv = xh[jb * 32 + lane];
                    aB0x += bf_lo(wv); aB0y += bf_hi(wv);
                }
            }
        }
        ((float2*)sm4[w][0])[lane] = make_float2(aA0x + aA1x, aA0y + aA1y);
        ((float2*)sm4[w][1])[lane] = make_float2(aB0x + aB1x, aB0y + aB1y);
        __syncwarp();

        // ------- dual GEMV1 (split accumulator chains) -------
        float2 hA = sb1[lane], hB = sb1[lane];
        float2 hA1 = make_float2(0.f, 0.f), hB1 = make_float2(0.f, 0.f);
        const float4* mAv = (const float4*)sm4[w][0];
        const float4* mBv = (const float4*)sm4[w][1];
        #pragma unroll
        for (int kk = 0; kk < 16; kk++) {
            float4 m4A = mAv[kk];
            float4 m4B = mBv[kk];
            float4 w0 = sW1q[2 * kk][lane];
            float4 w1 = sW1q[2 * kk + 1][lane];
            hA.x  = fmaf(m4A.x, w0.x, hA.x);  hA.y  = fmaf(m4A.x, w0.y, hA.y);
            hA1.x = fmaf(m4A.y, w0.z, hA1.x); hA1.y = fmaf(m4A.y, w0.w, hA1.y);
            hA.x  = fmaf(m4A.z, w1.x, hA.x);  hA.y  = fmaf(m4A.z, w1.y, hA.y);
            hA1.x = fmaf(m4A.w, w1.z, hA1.x); hA1.y = fmaf(m4A.w, w1.w, hA1.y);
            hB.x  = fmaf(m4B.x, w0.x, hB.x);  hB.y  = fmaf(m4B.x, w0.y, hB.y);
            hB1.x = fmaf(m4B.y, w0.z, hB1.x); hB1.y = fmaf(m4B.y, w0.w, hB1.y);
            hB.x  = fmaf(m4B.z, w1.x, hB.x);  hB.y  = fmaf(m4B.z, w1.y, hB.y);
            hB1.x = fmaf(m4B.w, w1.z, hB1.x); hB1.y = fmaf(m4B.w, w1.w, hB1.y);
        }
        hA.x += hA1.x; hA.y += hA1.y; hB.x += hB1.x; hB.y += hB1.y;
        hA.x = lrelu(hA.x); hA.y = lrelu(hA.y);
        hB.x = lrelu(hB.x); hB.y = lrelu(hB.y);
        ((float2*)sh4[w][0])[lane] = hA;
        ((float2*)sh4[w][1])[lane] = hB;
        __syncwarp();

        // ------- dual GEMV2 (split accumulator chains) -------
        float2 oA = sb2[lane], oB = sb2[lane];
        float2 oA1 = make_float2(0.f, 0.f), oB1 = make_float2(0.f, 0.f);
        const float4* hAv = (const float4*)sh4[w][0];
        const float4* hBv = (const float4*)sh4[w][1];
        #pragma unroll
        for (int kk = 0; kk < 16; kk++) {
            float4 m4A = hAv[kk];
            float4 m4B = hBv[kk];
            float4 w0 = sW2q[2 * kk][lane];
            float4 w1 = sW2q[2 * kk + 1][lane];
            oA.x  = fmaf(m4A.x, w0.x, oA.x);  oA.y  = fmaf(m4A.x, w0.y, oA.y);
            oA1.x = fmaf(m4A.y, w0.z, oA1.x); oA1.y = fmaf(m4A.y, w0.w, oA1.y);
            oA.x  = fmaf(m4A.z, w1.x, oA.x);  oA.y  = fmaf(m4A.z, w1.y, oA.y);
            oA1.x = fmaf(m4A.w, w1.z, oA1.x); oA1.y = fmaf(m4A.w, w1.w, oA1.y);
            oB.x  = fmaf(m4B.x, w0.x, oB.x);  oB.y  = fmaf(m4B.x, w0.y, oB.y);
            oB1.x = fmaf(m4B.y, w0.z, oB1.x); oB1.y = fmaf(m4B.y, w0.w, oB1.y);
            oB.x  = fmaf(m4B.z, w1.x, oB.x);  oB.y  = fmaf(m4B.z, w1.y, oB.y);
            oB1.x = fmaf(m4B.w, w1.z, oB1.x); oB1.y = fmaf(m4B.w, w1.w, oB1.y);
        }
        oA.x += oA1.x; oA.y += oA1.y; oB.x += oB1.x; oB.y += oB1.y;
        o2[nA * 32 + lane] = oA;
        ssx += oA.x; ssy += oA.y; sqx += oA.x * oA.x; sqy += oA.y * oA.y;
        if (hasB) {
            o2[nB * 32 + lane] = oB;
            ssx += oB.x; ssy += oB.y; sqx += oB.x * oB.x; sqy += oB.y * oB.y;
        }
        __syncwarp();
    }

    atomicAdd(&bstat[2 * lane], ssx);
    atomicAdd(&bstat[2 * lane + 1], ssy);
    atomicAdd(&bstat[64 + 2 * lane], sqx);
    atomicAdd(&bstat[64 + 2 * lane + 1], sqy);
    __syncthreads();
    if (tid < 128) atomicAdd(&g_stats[tid], bstat[tid]);
}

// ---------------- BN params (reads stats, then re-zeroes them) ----------------
__global__ void k_bnparams(const float* __restrict__ g, const float* __restrict__ b, int n) {
    int i = threadIdx.x;
    if (i < 64) {
        float inv = 1.0f / (float)n;
        float mean = g_stats[i] * inv;
        float var = g_stats[64 + i] * inv - mean * mean;
        float sc = g[i] * rsqrtf(var + 1e-5f);
        g_stats[128 + i] = sc;
        g_stats[192 + i] = b[i] - sc * mean;
        g_stats[i] = 0.f;
        g_stats[64 + i] = 0.f;
    }
}

// ---------------- BN + leaky (fp32 in-place + bf16 copy) ----------------------
__global__ void k_bnapply(int lz, int n) {
    int i = blockIdx.x * blockDim.x + threadIdx.x;
    if (i >= n * 32) return;
    int c = (i & 31) * 2;
    float2* z2 = (float2*)g_z[lz];
    float2 v = z2[i];
    v.x = lrelu(g_stats[128 + c] * v.x + g_stats[192 + c]);
    v.y = lrelu(g_stats[128 + c + 1] * v.y + g_stats[192 + c + 1]);
    z2[i] = v;
    g_zh[lz][i] = pack_bf16x2(v);
}

// ---------------- FC layer 1 (two 128-row chunks, dual-node) ------------------
__global__ void __launch_bounds__(256) k_fc(
    const float* __restrict__ fcW1, const float* __restrict__ fcb1, int chunk, int n)
{
    __shared__ float4 sWq[64][32];
    __shared__ float4 sx4[8][2][32];
    __shared__ float2 sb[32];
    __shared__ float  bstat[128];
    int tid = threadIdx.x;
    {
        const float2* wv = (const float2*)(fcW1 + chunk * 128 * 64);
        for (int i = tid; i < 2048; i += 256) {
            int k2 = i >> 5, c = i & 31;
            float2 a = wv[(2 * k2) * 32 + c];
            float2 b = wv[(2 * k2 + 1) * 32 + c];
            sWq[k2][c] = make_float4(a.x, a.y, b.x, b.y);
        }
        if (tid < 32) sb[tid] = (chunk == 0) ? ((const float2*)fcb1)[tid] : make_float2(0.f, 0.f);
        if (tid < 128) bstat[tid] = 0.f;
    }
    __syncthreads();

    const float2* za = (const float2*)g_z[2 * chunk];
    const float2* zb = (const float2*)g_z[2 * chunk + 1];
    float2* u2 = (float2*)g_u;
    int w = tid >> 5, lane = tid & 31;
    float ssx = 0.f, ssy = 0.f, sqx = 0.f, sqy = 0.f;
    int gw = (blockIdx.x * 256 + tid) >> 5;
    int nw = (gridDim.x * 256) >> 5;

    for (int base = gw * 2; base < n; base += nw * 2) {
        int nA = base, nB = base + 1;
        bool hasB = (nB < n);
        ((float2*)sx4[w][0])[lane]      = za[nA * 32 + lane];
        ((float2*)sx4[w][0])[32 + lane] = zb[nA * 32 + lane];
        if (hasB) {
            ((float2*)sx4[w][1])[lane]      = za[nB * 32 + lane];
            ((float2*)sx4[w][1])[32 + lane] = zb[nB * 32 + lane];
        }
        __syncwarp();

        float2 uA = (chunk == 0) ? sb[lane] : u2[nA * 32 + lane];
        float2 uB = (chunk == 0) ? sb[lane] : (hasB ? u2[nB * 32 + lane] : make_float2(0.f, 0.f));
        float2 uA1 = make_float2(0.f, 0.f), uB1 = make_float2(0.f, 0.f);
        const float4* xAv = (const float4*)sx4[w][0];
        const float4* xBv = (const float4*)sx4[w][1];
        #pragma unroll
        for (int kk = 0; kk < 32; kk++) {
            float4 m4A = xAv[kk];
            float4 m4B = xBv[kk];
            float4 w0 = sWq[2 * kk][lane];
            float4 w1 = sWq[2 * kk + 1][lane];
            uA.x  = fmaf(m4A.x, w0.x, uA.x);  uA.y  = fmaf(m4A.x, w0.y, uA.y);
            uA1.x = fmaf(m4A.y, w0.z, uA1.x); uA1.y = fmaf(m4A.y, w0.w, uA1.y);
            uA.x  = fmaf(m4A.z, w1.x, uA.x);  uA.y  = fmaf(m4A.z, w1.y, uA.y);
            uA1.x = fmaf(m4A.w, w1.z, uA1.x); uA1.y = fmaf(m4A.w, w1.w, uA1.y);
            uB.x  = fmaf(m4B.x, w0.x, uB.x);  uB.y  = fmaf(m4B.x, w0.y, uB.y);
            uB1.x = fmaf(m4B.y, w0.z, uB1.x); uB1.y = fmaf(m4B.y, w0.w, uB1.y);
            uB.x  = fmaf(m4B.z, w1.x, uB.x);  uB.y  = fmaf(m4B.z, w1.y, uB.y);
            uB1.x = fmaf(m4B.w, w1.z, uB1.x); uB1.y = fmaf(m4B.w, w1.w, uB1.y);
        }
        uA.x += uA1.x; uA.y += uA1.y; uB.x += uB1.x; uB.y += uB1.y;
        u2[nA * 32 + lane] = uA;
        if (chunk == 1) { ssx += uA.x; ssy += uA.y; sqx += uA.x * uA.x; sqy += uA.y * uA.y; }
        if (hasB) {
            u2[nB * 32 + lane] = uB;
            if (chunk == 1) { ssx += uB.x; ssy += uB.y; sqx += uB.x * uB.x; sqy += uB.y * uB.y; }
        }
        __syncwarp();
    }

    if (chunk == 1) {
        atomicAdd(&bstat[2 * lane], ssx);
        atomicAdd(&bstat[2 * lane + 1], ssy);
        atomicAdd(&bstat[64 + 2 * lane], sqx);
        atomicAdd(&bstat[64 + 2 * lane + 1], sqy);
        __syncthreads();
        if (tid < 128) atomicAdd(&g_stats[tid], bstat[tid]);
    }
}

// ---------------- head --------------------------------------------------------
__global__ void k_head(const float* __restrict__ fcW2, const float* __restrict__ fcb2,
                       float* __restrict__ out, int n) {
    int gt = blockIdx.x * blockDim.x + threadIdx.x;
    int node = gt >> 5, lane = gt & 31;
    if (node >= n) return;
    float2 u = ((const float2*)g_u)[node * 32 + lane];
    int c = 2 * lane;
    float y0 = lrelu(g_stats[128 + c] * u.x + g_stats[192 + c]);
    float y1 = lrelu(g_stats[128 + c + 1] * u.y + g_stats[192 + c + 1]);
    float p = y0 * fcW2[c] + y1 * fcW2[c + 1];
    #pragma unroll
    for (int o = 16; o > 0; o >>= 1) p += __shfl_xor_sync(0xffffffffu, p, o);
    if (lane == 0) out[node] = 1.0f / (1.0f + expf(-(p + fcb2[0])));
}

// ---------------- launch -------------------------------------------------------
extern "C" void kernel_launch(void* const* d_in, const int* in_sizes, int n_in,
                              void* d_out, int out_size) {
    const int*   node_deg = (const int*)d_in[0];
    const int*   edge_idx = (const int*)d_in[1];
    const float* embed    = (const float*)d_in[2];
    const float* eps      = (const float*)d_in[3];
    const float* W1       = (const float*)d_in[4];
    const float* b1       = (const float*)d_in[5];
    const float* W2       = (const float*)d_in[6];
    const float* b2       = (const float*)d_in[7];
    const float* bn_g     = (const float*)d_in[8];
    const float* bn_b     = (const float*)d_in[9];
    const float* fcW1     = (const float*)d_in[10];
    const float* fcb1     = (const float*)d_in[11];
    const float* fc_bn_g  = (const float*)d_in[12];
    const float* fc_bn_b  = (const float*)d_in[13];
    const float* fcW2     = (const float*)d_in[14];
    const float* fcb2     = (const float*)d_in[15];

    int n = in_sizes[0];
    int e = in_sizes[1] / 2;
    const int* src = edge_idx;
    const int* dst = edge_idx + e;

    int elemBlocks = (n * 32 + 255) / 256;
    int nb = (n + 1023) / 1024;
    const int PGRID = 592;

    bool vec4 = ((e & 3) == 0)
             && ((((unsigned long long)(size_t)src) & 15ull) == 0)
             && ((((unsigned long long)(size_t)dst) & 15ull) == 0);

    k_zero_deg<<<(n + 255) / 256, 256>>>(n);
    if (vec4) k_hist4<<<1024, 256>>>(dst, e / 4, e);
    else      k_hist<<<1024, 256>>>(dst, e);
    k_scan1<<<nb, 1024>>>(n);
    k_scan2<<<1, 128>>>(nb);
    k_scan3<<<nb, 1024>>>(n, e);
    if (vec4) k_fill4<<<1024, 256>>>(src, dst, e / 4, e);
    else      k_fill<<<1024, 256>>>(src, dst, e);

    k_embed<<<elemBlocks, 256>>>(node_deg, embed, n);

    for (int l = 0; l < 3; l++) {
        k_layer<<<PGRID, 256>>>(W1, b1, W2, b2, eps, l, n);
        k_bnparams<<<1, 64>>>(bn_g + l * 64, bn_b + l * 64, n);
        k_bnapply<<<elemBlocks, 256>>>(l + 1, n);
    }

    k_fc<<<PGRID, 256>>>(fcW1, fcb1, 0, n);
    k_fc<<<PGRID, 256>>>(fcW1, fcb1, 1, n);
    k_bnparams<<<1, 64>>>(fc_bn_g, fc_bn_b, n);
    k_head<<<elemBlocks, 256>>>(fcW2, fcb2, (float*)d_out, n);
}

// round 10
// speedup vs baseline: 1.5356x; 1.5356x over previous
#include <cuda_runtime.h>
#include <cuda_bf16.h>
#include <stdint.h>
#include <math.h>

#define MAXN 100000
#define MAXE 3200000

// ---------------- scratch (static device globals) ---------------------------
__device__ int          g_cursor[MAXN];
__device__ int          g_rowptr[MAXN + 1];
__device__ int          g_col[MAXE];
__device__ int          g_bsum[256];
__device__ float        g_z[4][MAXN * 64];     // fp32 master copies z0..z3
__device__ unsigned int g_zh[4][MAXN * 32];    // bf16x2 gather copies
__device__ float        g_u[MAXN * 64];
__device__ float        g_stats[256];          // sum | sumsq | scale | shift

__device__ __forceinline__ float lrelu(float x) { return x >= 0.f ? x : 0.01f * x; }

__device__ __forceinline__ unsigned int pack_bf16x2(float2 v) {
    __nv_bfloat162 b = __float22bfloat162_rn(v);
    return *(unsigned int*)&b;
}
__device__ __forceinline__ float bf_lo(unsigned int w) { return __int_as_float((int)(w << 16)); }
__device__ __forceinline__ float bf_hi(unsigned int w) { return __int_as_float((int)(w & 0xffff0000u)); }

// ---------------- CSR build --------------------------------------------------
__global__ void k_zero_deg(int n) {
    int i = blockIdx.x * blockDim.x + threadIdx.x;
    if (i < n) g_cursor[i] = 0;
}

__global__ void k_hist4(const int* __restrict__ dst, int e4, int e) {
    int stride = gridDim.x * blockDim.x;
    int t0 = blockIdx.x * blockDim.x + threadIdx.x;
    const int4* d4 = (const int4*)dst;
    for (int i = t0; i < e4; i += stride) {
        int4 d = d4[i];
        atomicAdd(&g_cursor[d.x], 1);
        atomicAdd(&g_cursor[d.y], 1);
        atomicAdd(&g_cursor[d.z], 1);
        atomicAdd(&g_cursor[d.w], 1);
    }
    for (int i = e4 * 4 + t0; i < e; i += stride)
        atomicAdd(&g_cursor[dst[i]], 1);
}

__global__ void k_scan1(int n) {
    __shared__ int wsum[32];
    int tid = threadIdx.x, lane = tid & 31, w = tid >> 5;
    int i = blockIdx.x * 1024 + tid;
    int v = (i < n) ? g_cursor[i] : 0;
    int x = v;
    #pragma unroll
    for (int off = 1; off < 32; off <<= 1) {
        int t = __shfl_up_sync(0xffffffffu, x, off);
        if (lane >= off) x += t;
    }
    if (lane == 31) wsum[w] = x;
    __syncthreads();
    if (w == 0) {
        int s = wsum[lane];
        #pragma unroll
        for (int off = 1; off < 32; off <<= 1) {
            int t = __shfl_up_sync(0xffffffffu, s, off);
            if (lane >= off) s += t;
        }
        wsum[lane] = s;
    }
    __syncthreads();
    int incl = x + (w > 0 ? wsum[w - 1] : 0);
    if (i < n) g_rowptr[i] = incl - v;
    if (tid == 1023) g_bsum[blockIdx.x] = incl;
}

__global__ void k_scan2(int nb) {
    __shared__ int ws[4];
    int tid = threadIdx.x, lane = tid & 31, w = tid >> 5;
    int v = (tid < nb) ? g_bsum[tid] : 0;
    int x = v;
    #pragma unroll
    for (int off = 1; off < 32; off <<= 1) {
        int t = __shfl_up_sync(0xffffffffu, x, off);
        if (lane >= off) x += t;
    }
    if (lane == 31) ws[w] = x;
    __syncthreads();
    if (tid == 0) {
        int c = 0;
        #pragma unroll
        for (int k = 0; k < 4; k++) { int t = ws[k]; ws[k] = c; c += t; }
    }
    __syncthreads();
    if (tid < nb) g_bsum[tid] = x - v + ws[w];
}

__global__ void k_scan3(int n, int e) {
    int i = blockIdx.x * 1024 + threadIdx.x;
    if (i < n) {
        int v = g_rowptr[i] + g_bsum[blockIdx.x];
        g_rowptr[i] = v;
        g_cursor[i] = v;
    }
    if (i == 0) g_rowptr[n] = e;
}

__global__ void k_fill4(const int* __restrict__ src, const int* __restrict__ dst, int e4, int e) {
    int stride = gridDim.x * blockDim.x;
    int t0 = blockIdx.x * blockDim.x + threadIdx.x;
    const int4* s4 = (const int4*)src;
    const int4* d4 = (const int4*)dst;
    for (int i = t0; i < e4; i += stride) {
        int4 d = d4[i];
        int4 s = s4[i];
        int p0 = atomicAdd(&g_cursor[d.x], 1);
        int p1 = atomicAdd(&g_cursor[d.y], 1);
        int p2 = atomicAdd(&g_cursor[d.z], 1);
        int p3 = atomicAdd(&g_cursor[d.w], 1);
        g_col[p0] = s.x; g_col[p1] = s.y; g_col[p2] = s.z; g_col[p3] = s.w;
    }
    for (int i = e4 * 4 + t0; i < e; i += stride) {
        int p = atomicAdd(&g_cursor[dst[i]], 1);
        g_col[p] = src[i];
    }
}

__global__ void k_hist(const int* __restrict__ dst, int e) {
    int stride = gridDim.x * blockDim.x;
    for (int i = blockIdx.x * blockDim.x + threadIdx.x; i < e; i += stride)
        atomicAdd(&g_cursor[dst[i]], 1);
}
__global__ void k_fill(const int* __restrict__ src, const int* __restrict__ dst, int e) {
    int stride = gridDim.x * blockDim.x;
    for (int i = blockIdx.x * blockDim.x + threadIdx.x; i < e; i += stride) {
        int p = atomicAdd(&g_cursor[dst[i]], 1);
        g_col[p] = src[i];
    }
}

// ---------------- embedding lookup (also zeroes stats) -----------------------
__global__ void k_embed(const int* __restrict__ deg, const float* __restrict__ emb, int n) {
    if (blockIdx.x == 0 && threadIdx.x < 128) g_stats[threadIdx.x] = 0.f;
    int i = blockIdx.x * blockDim.x + threadIdx.x;
    if (i >= n * 32) return;
    int node = i >> 5, j = i & 31;
    float2 v = ((const float2*)emb)[deg[node] * 32 + j];
    ((float2*)g_z[0])[i] = v;
    g_zh[0][i] = pack_bf16x2(v);
}

// ---------------- fused GIN layer: interleaved gather + dual GEMVs ------------
__global__ void __launch_bounds__(256) k_layer(
    const float* __restrict__ W1, const float* __restrict__ b1,
    const float* __restrict__ W2, const float* __restrict__ b2,
    const float* __restrict__ epsArr, int l, int n)
{
    __shared__ float4 sW1q[32][32];
    __shared__ float4 sW2q[32][32];
    __shared__ float2 sb1[32];
    __shared__ float2 sb2[32];
    __shared__ float4 sm4[8][2][16];
    __shared__ float4 sh4[8][2][16];
    __shared__ float  bstat[128];

    int tid = threadIdx.x;
    {
        const float2* w1v = (const float2*)(W1 + l * 4096);
        const float2* w2v = (const float2*)(W2 + l * 4096);
        for (int i = tid; i < 1024; i += 256) {
            int k2 = i >> 5, c = i & 31;
            float2 a = w1v[(2 * k2) * 32 + c];
            float2 b = w1v[(2 * k2 + 1) * 32 + c];
            sW1q[k2][c] = make_float4(a.x, a.y, b.x, b.y);
            float2 a2 = w2v[(2 * k2) * 32 + c];
            float2 b2v = w2v[(2 * k2 + 1) * 32 + c];
            sW2q[k2][c] = make_float4(a2.x, a2.y, b2v.x, b2v.y);
        }
        if (tid < 32) {
            sb1[tid] = ((const float2*)(b1 + l * 64))[tid];
            sb2[tid] = ((const float2*)(b2 + l * 64))[tid];
        }
        if (tid < 128) bstat[tid] = 0.f;
    }
    __syncthreads();

    float ep = 1.0f + epsArr[l];
    const float2*       __restrict__ x2 = (const float2*)g_z[l];
    const unsigned int* __restrict__ xh = g_zh[l];
    float2* o2 = (float2*)g_z[l + 1];
    int w = tid >> 5, lane = tid & 31;
    float ssx = 0.f, ssy = 0.f, sqx = 0.f, sqy = 0.f;
    int gw = (blockIdx.x * 256 + tid) >> 5;
    int nw = (gridDim.x * 256) >> 5;

    for (int base = gw * 2; base < n; base += nw * 2) {
        int nA = base, nB = base + 1;
        bool hasB = (nB < n);

        // ------- interleaved dual-node gather (MLP = 8) -------
        int bA = g_rowptr[nA], reA = g_rowptr[nA + 1];
        int bB = hasB ? g_rowptr[nB] : 0, reB = hasB ? g_rowptr[nB + 1] : 0;
        float2 xvA = x2[nA * 32 + lane];
        float2 xvB = hasB ? x2[nB * 32 + lane] : make_float2(0.f, 0.f);
        float aA0x = ep * xvA.x, aA0y = ep * xvA.y, aA1x = 0.f, aA1y = 0.f;
        float aB0x = ep * xvB.x, aB0y = ep * xvB.y, aB1x = 0.f, aB1y = 0.f;

        while (bA + 32 <= reA && bB + 32 <= reB) {
            int jA = g_col[bA + lane];
            int jB = g_col[bB + lane];
            #pragma unroll
            for (int t = 0; t < 32; t += 2) {
                int a0 = __shfl_sync(0xffffffffu, jA, t);
                int a1 = __shfl_sync(0xffffffffu, jA, t + 1);
                int c0 = __shfl_sync(0xffffffffu, jB, t);
                int c1 = __shfl_sync(0xffffffffu, jB, t + 1);
                unsigned int wA0 = xh[a0 * 32 + lane];
                unsigned int wA1 = xh[a1 * 32 + lane];
                unsigned int wB0 = xh[c0 * 32 + lane];
                unsigned int wB1 = xh[c1 * 32 + lane];
                aA0x += bf_lo(wA0); aA0y += bf_hi(wA0);
                aA1x += bf_lo(wA1); aA1y += bf_hi(wA1);
                aB0x += bf_lo(wB0); aB0y += bf_hi(wB0);
                aB1x += bf_lo(wB1); aB1y += bf_hi(wB1);
            }
            bA += 32; bB += 32;
        }
        while (bA + 32 <= reA) {
            int jA = g_col[bA + lane];
            #pragma unroll
            for (int t = 0; t < 32; t += 4) {
                int a0 = __shfl_sync(0xffffffffu, jA, t);
                int a1 = __shfl_sync(0xffffffffu, jA, t + 1);
                int a2 = __shfl_sync(0xffffffffu, jA, t + 2);
                int a3 = __shfl_sync(0xffffffffu, jA, t + 3);
                unsigned int w0 = xh[a0 * 32 + lane];
                unsigned int w1 = xh[a1 * 32 + lane];
                unsigned int w2 = xh[a2 * 32 + lane];
                unsigned int w3 = xh[a3 * 32 + lane];
                aA0x += bf_lo(w0); aA0y += bf_hi(w0);
                aA1x += bf_lo(w1); aA1y += bf_hi(w1);
                aA0x += bf_lo(w2); aA0y += bf_hi(w2);
                aA1x += bf_lo(w3); aA1y += bf_hi(w3);
            }
            bA += 32;
        }
        while (bB + 32 <= reB) {
            int jB = g_col[bB + lane];
            #pragma unroll
            for (int t = 0; t < 32; t += 4) {
                int a0 = __shfl_sync(0xffffffffu, jB, t);
                int a1 = __shfl_sync(0xffffffffu, jB, t + 1);
                int a2 = __shfl_sync(0xffffffffu, jB, t + 2);
                int a3 = __shfl_sync(0xffffffffu, jB, t + 3);
                unsigned int w0 = xh[a0 * 32 + lane];
                unsigned int w1 = xh[a1 * 32 + lane];
                unsigned int w2 = xh[a2 * 32 + lane];
                unsigned int w3 = xh[a3 * 32 + lane];
                aB0x += bf_lo(w0); aB0y += bf_hi(w0);
                aB1x += bf_lo(w1); aB1y += bf_hi(w1);
                aB0x += bf_lo(w2); aB0y += bf_hi(w2);
                aB1x += bf_lo(w3); aB1y += bf_hi(w3);
            }
            bB += 32;
        }
        {   // interleaved tails (<32 each)
            int remA = reA - bA, remB = reB - bB;
            int jA = (lane < remA) ? g_col[bA + lane] : 0;
            int jB = (lane < remB) ? g_col[bB + lane] : 0;
            int rem = remA > remB ? remA : remB;
            for (int t = 0; t < rem; t++) {
                int ja = __shfl_sync(0xffffffffu, jA, t);
                int jb = __shfl_sync(0xffffffffu, jB, t);
                if (t < remA) {
                    unsigned int wv = xh[ja * 32 + lane];
                    aA0x += bf_lo(wv); aA0y += bf_hi(wv);
                }
                if (t < remB) {
                    unsigned int wv = xh[jb * 32 + lane];
                    aB0x += bf_lo(wv); aB0y += bf_hi(wv);
                }
            }
        }
        ((float2*)sm4[w][0])[lane] = make_float2(aA0x + aA1x, aA0y + aA1y);
        ((float2*)sm4[w][1])[lane] = make_float2(aB0x + aB1x, aB0y + aB1y);
        __syncwarp();

        // ------- dual GEMV1 -------
        float2 hA = sb1[lane], hB = sb1[lane];
        const float4* mAv = (const float4*)sm4[w][0];
        const float4* mBv = (const float4*)sm4[w][1];
        #pragma unroll
        for (int kk = 0; kk < 16; kk++) {
            float4 m4A = mAv[kk];
            float4 m4B = mBv[kk];
            float4 w0 = sW1q[2 * kk][lane];
            float4 w1 = sW1q[2 * kk + 1][lane];
            hA.x = fmaf(m4A.x, w0.x, hA.x); hA.y = fmaf(m4A.x, w0.y, hA.y);
            hA.x = fmaf(m4A.y, w0.z, hA.x); hA.y = fmaf(m4A.y, w0.w, hA.y);
            hA.x = fmaf(m4A.z, w1.x, hA.x); hA.y = fmaf(m4A.z, w1.y, hA.y);
            hA.x = fmaf(m4A.w, w1.z, hA.x); hA.y = fmaf(m4A.w, w1.w, hA.y);
            hB.x = fmaf(m4B.x, w0.x, hB.x); hB.y = fmaf(m4B.x, w0.y, hB.y);
            hB.x = fmaf(m4B.y, w0.z, hB.x); hB.y = fmaf(m4B.y, w0.w, hB.y);
            hB.x = fmaf(m4B.z, w1.x, hB.x); hB.y = fmaf(m4B.z, w1.y, hB.y);
            hB.x = fmaf(m4B.w, w1.z, hB.x); hB.y = fmaf(m4B.w, w1.w, hB.y);
        }
        hA.x = lrelu(hA.x); hA.y = lrelu(hA.y);
        hB.x = lrelu(hB.x); hB.y = lrelu(hB.y);
        ((float2*)sh4[w][0])[lane] = hA;
        ((float2*)sh4[w][1])[lane] = hB;
        __syncwarp();

        // ------- dual GEMV2 -------
        float2 oA = sb2[lane], oB = sb2[lane];
        const float4* hAv = (const float4*)sh4[w][0];
        const float4* hBv = (const float4*)sh4[w][1];
        #pragma unroll
        for (int kk = 0; kk < 16; kk++) {
            float4 m4A = hAv[kk];
            float4 m4B = hBv[kk];
            float4 w0 = sW2q[2 * kk][lane];
            float4 w1 = sW2q[2 * kk + 1][lane];
            oA.x = fmaf(m4A.x, w0.x, oA.x); oA.y = fmaf(m4A.x, w0.y, oA.y);
            oA.x = fmaf(m4A.y, w0.z, oA.x); oA.y = fmaf(m4A.y, w0.w, oA.y);
            oA.x = fmaf(m4A.z, w1.x, oA.x); oA.y = fmaf(m4A.z, w1.y, oA.y);
            oA.x = fmaf(m4A.w, w1.z, oA.x); oA.y = fmaf(m4A.w, w1.w, oA.y);
            oB.x = fmaf(m4B.x, w0.x, oB.x); oB.y = fmaf(m4B.x, w0.y, oB.y);
            oB.x = fmaf(m4B.y, w0.z, oB.x); oB.y = fmaf(m4B.y, w0.w, oB.y);
            oB.x = fmaf(m4B.z, w1.x, oB.x); oB.y = fmaf(m4B.z, w1.y, oB.y);
            oB.x = fmaf(m4B.w, w1.z, oB.x); oB.y = fmaf(m4B.w, w1.w, oB.y);
        }
        o2[nA * 32 + lane] = oA;
        ssx += oA.x; ssy += oA.y; sqx += oA.x * oA.x; sqy += oA.y * oA.y;
        if (hasB) {
            o2[nB * 32 + lane] = oB;
            ssx += oB.x; ssy += oB.y; sqx += oB.x * oB.x; sqy += oB.y * oB.y;
        }
        __syncwarp();
    }

    atomicAdd(&bstat[2 * lane], ssx);
    atomicAdd(&bstat[2 * lane + 1], ssy);
    atomicAdd(&bstat[64 + 2 * lane], sqx);
    atomicAdd(&bstat[64 + 2 * lane + 1], sqy);
    __syncthreads();
    if (tid < 128) atomicAdd(&g_stats[tid], bstat[tid]);
}

// ---------------- BN params (reads stats, then re-zeroes them) ----------------
__global__ void k_bnparams(const float* __restrict__ g, const float* __restrict__ b, int n) {
    int i = threadIdx.x;
    if (i < 64) {
        float inv = 1.0f / (float)n;
        float mean = g_stats[i] * inv;
        float var = g_stats[64 + i] * inv - mean * mean;
        float sc = g[i] * rsqrtf(var + 1e-5f);
        g_stats[128 + i] = sc;
        g_stats[192 + i] = b[i] - sc * mean;
        g_stats[i] = 0.f;
        g_stats[64 + i] = 0.f;
    }
}

// ---------------- BN + leaky (fp32 in-place + bf16 copy) ----------------------
__global__ void k_bnapply(int lz, int n) {
    int i = blockIdx.x * blockDim.x + threadIdx.x;
    if (i >= n * 32) return;
    int c = (i & 31) * 2;
    float2* z2 = (float2*)g_z[lz];
    float2 v = z2[i];
    v.x = lrelu(g_stats[128 + c] * v.x + g_stats[192 + c]);
    v.y = lrelu(g_stats[128 + c + 1] * v.y + g_stats[192 + c + 1]);
    z2[i] = v;
    g_zh[lz][i] = pack_bf16x2(v);
}

// ---------------- FC layer 1 (two 128-row chunks, dual-node) ------------------
__global__ void __launch_bounds__(256) k_fc(
    const float* __restrict__ fcW1, const float* __restrict__ fcb1, int chunk, int n)
{
    __shared__ float4 sWq[64][32];
    __shared__ float4 sx4[8][2][32];
    __shared__ float2 sb[32];
    __shared__ float  bstat[128];
    int tid = threadIdx.x;
    {
        const float2* wv = (const float2*)(fcW1 + chunk * 128 * 64);
        for (int i = tid; i < 2048; i += 256) {
            int k2 = i >> 5, c = i & 31;
            float2 a = wv[(2 * k2) * 32 + c];
            float2 b = wv[(2 * k2 + 1) * 32 + c];
            sWq[k2][c] = make_float4(a.x, a.y, b.x, b.y);
        }
        if (tid < 32) sb[tid] = (chunk == 0) ? ((const float2*)fcb1)[tid] : make_float2(0.f, 0.f);
        if (tid < 128) bstat[tid] = 0.f;
    }
    __syncthreads();

    const float2* za = (const float2*)g_z[2 * chunk];
    const float2* zb = (const float2*)g_z[2 * chunk + 1];
    float2* u2 = (float2*)g_u;
    int w = tid >> 5, lane = tid & 31;
    float ssx = 0.f, ssy = 0.f, sqx = 0.f, sqy = 0.f;
    int gw = (blockIdx.x * 256 + tid) >> 5;
    int nw = (gridDim.x * 256) >> 5;

    for (int base = gw * 2; base < n; base += nw * 2) {
        int nA = base, nB = base + 1;
        bool hasB = (nB < n);
        ((float2*)sx4[w][0])[lane]      = za[nA * 32 + lane];
        ((float2*)sx4[w][0])[32 + lane] = zb[nA * 32 + lane];
        if (hasB) {
            ((float2*)sx4[w][1])[lane]      = za[nB * 32 + lane];
            ((float2*)sx4[w][1])[32 + lane] = zb[nB * 32 + lane];
        }
        __syncwarp();

        float2 uA = (chunk == 0) ? sb[lane] : u2[nA * 32 + lane];
        float2 uB = (chunk == 0) ? sb[lane] : (hasB ? u2[nB * 32 + lane] : make_float2(0.f, 0.f));
        const float4* xAv = (const float4*)sx4[w][0];
        const float4* xBv = (const float4*)sx4[w][1];
        #pragma unroll
        for (int kk = 0; kk < 32; kk++) {
            float4 m4A = xAv[kk];
            float4 m4B = xBv[kk];
            float4 w0 = sWq[2 * kk][lane];
            float4 w1 = sWq[2 * kk + 1][lane];
            uA.x = fmaf(m4A.x, w0.x, uA.x); uA.y = fmaf(m4A.x, w0.y, uA.y);
            uA.x = fmaf(m4A.y, w0.z, uA.x); uA.y = fmaf(m4A.y, w0.w, uA.y);
            uA.x = fmaf(m4A.z, w1.x, uA.x); uA.y = fmaf(m4A.z, w1.y, uA.y);
            uA.x = fmaf(m4A.w, w1.z, uA.x); uA.y = fmaf(m4A.w, w1.w, uA.y);
            uB.x = fmaf(m4B.x, w0.x, uB.x); uB.y = fmaf(m4B.x, w0.y, uB.y);
            uB.x = fmaf(m4B.y, w0.z, uB.x); uB.y = fmaf(m4B.y, w0.w, uB.y);
            uB.x = fmaf(m4B.z, w1.x, uB.x); uB.y = fmaf(m4B.z, w1.y, uB.y);
            uB.x = fmaf(m4B.w, w1.z, uB.x); uB.y = fmaf(m4B.w, w1.w, uB.y);
        }
        u2[nA * 32 + lane] = uA;
        if (chunk == 1) { ssx += uA.x; ssy += uA.y; sqx += uA.x * uA.x; sqy += uA.y * uA.y; }
        if (hasB) {
            u2[nB * 32 + lane] = uB;
            if (chunk == 1) { ssx += uB.x; ssy += uB.y; sqx += uB.x * uB.x; sqy += uB.y * uB.y; }
        }
        __syncwarp();
    }

    if (chunk == 1) {
        atomicAdd(&bstat[2 * lane], ssx);
        atomicAdd(&bstat[2 * lane + 1], ssy);
        atomicAdd(&bstat[64 + 2 * lane], sqx);
        atomicAdd(&bstat[64 + 2 * lane + 1], sqy);
        __syncthreads();
        if (tid < 128) atomicAdd(&g_stats[tid], bstat[tid]);
    }
}

// ---------------- head --------------------------------------------------------
__global__ void k_head(const float* __restrict__ fcW2, const float* __restrict__ fcb2,
                       float* __restrict__ out, int n) {
    int gt = blockIdx.x * blockDim.x + threadIdx.x;
    int node = gt >> 5, lane = gt & 31;
    if (node >= n) return;
    float2 u = ((const float2*)g_u)[node * 32 + lane];
    int c = 2 * lane;
    float y0 = lrelu(g_stats[128 + c] * u.x + g_stats[192 + c]);
    float y1 = lrelu(g_stats[128 + c + 1] * u.y + g_stats[192 + c + 1]);
    float p = y0 * fcW2[c] + y1 * fcW2[c + 1];
    #pragma unroll
    for (int o = 16; o > 0; o >>= 1) p += __shfl_xor_sync(0xffffffffu, p, o);
    if (lane == 0) out[node] = 1.0f / (1.0f + expf(-(p + fcb2[0])));
}

// ---------------- launch -------------------------------------------------------
extern "C" void kernel_launch(void* const* d_in, const int* in_sizes, int n_in,
                              void* d_out, int out_size) {
    const int*   node_deg = (const int*)d_in[0];
    const int*   edge_idx = (const int*)d_in[1];
    const float* embed    = (const float*)d_in[2];
    const float* eps      = (const float*)d_in[3];
    const float* W1       = (const float*)d_in[4];
    const float* b1       = (const float*)d_in[5];
    const float* W2       = (const float*)d_in[6];
    const float* b2       = (const float*)d_in[7];
    const float* bn_g     = (const float*)d_in[8];
    const float* bn_b     = (const float*)d_in[9];
    const float* fcW1     = (const float*)d_in[10];
    const float* fcb1     = (const float*)d_in[11];
    const float* fc_bn_g  = (const float*)d_in[12];
    const float* fc_bn_b  = (const float*)d_in[13];
    const float* fcW2     = (const float*)d_in[14];
    const float* fcb2     = (const float*)d_in[15];

    int n = in_sizes[0];
    int e = in_sizes[1] / 2;
    const int* src = edge_idx;
    const int* dst = edge_idx + e;

    int elemBlocks = (n * 32 + 255) / 256;
    int nb = (n + 1023) / 1024;
    const int PGRID = 592;

    bool vec4 = ((e & 3) == 0)
             && ((((unsigned long long)(size_t)src) & 15ull) == 0)
             && ((((unsigned long long)(size_t)dst) & 15ull) == 0);

    k_zero_deg<<<(n + 255) / 256, 256>>>(n);
    if (vec4) k_hist4<<<1024, 256>>>(dst, e / 4, e);
    else      k_hist<<<1024, 256>>>(dst, e);
    k_scan1<<<nb, 1024>>>(n);
    k_scan2<<<1, 128>>>(nb);
    k_scan3<<<nb, 1024>>>(n, e);
    if (vec4) k_fill4<<<1024, 256>>>(src, dst, e / 4, e);
    else      k_fill<<<1024, 256>>>(src, dst, e);

    k_embed<<<elemBlocks, 256>>>(node_deg, embed, n);

    for (int l = 0; l < 3; l++) {
        k_layer<<<PGRID, 256>>>(W1, b1, W2, b2, eps, l, n);
        k_bnparams<<<1, 64>>>(bn_g + l * 64, bn_b + l * 64, n);
        k_bnapply<<<elemBlocks, 256>>>(l + 1, n);
    }

    k_fc<<<PGRID, 256>>>(fcW1, fcb1, 0, n);
    k_fc<<<PGRID, 256>>>(fcW1, fcb1, 1, n);
    k_bnparams<<<1, 64>>>(fc_bn_g, fc_bn_b, n);
    k_head<<<elemBlocks, 256>>>(fcW2, fcb2, (float*)d_out, n);
}

// round 11
// speedup vs baseline: 1.5681x; 1.0212x over previous
#include <cuda_runtime.h>
#include <cuda_bf16.h>
#include <stdint.h>
#include <math.h>

#define MAXN 100000
#define MAXE 3200000

// ---------------- scratch (static device globals) ---------------------------
__device__ int          g_cursor[MAXN];
__device__ int          g_rowptr[MAXN + 1];
__device__ int          g_col[MAXE];
__device__ int          g_bsum[256];
__device__ float        g_z[4][MAXN * 64];     // fp32 master copies z0..z3
__device__ unsigned int g_zh[4][MAXN * 32];    // bf16x2 gather copies
__device__ float        g_u[MAXN * 64];
__device__ float        g_stats[256];          // sum | sumsq | scale | shift

__device__ __forceinline__ float lrelu(float x) { return x >= 0.f ? x : 0.01f * x; }

__device__ __forceinline__ unsigned int pack_bf16x2(float2 v) {
    __nv_bfloat162 b = __float22bfloat162_rn(v);
    return *(unsigned int*)&b;
}
__device__ __forceinline__ float bf_lo(unsigned int w) { return __int_as_float((int)(w << 16)); }
__device__ __forceinline__ float bf_hi(unsigned int w) { return __int_as_float((int)(w & 0xffff0000u)); }

// ---------------- CSR build --------------------------------------------------
__global__ void k_zero_deg(int n) {
    int i = blockIdx.x * blockDim.x + threadIdx.x;
    if (i < n) g_cursor[i] = 0;
}

__global__ void k_hist4(const int* __restrict__ dst, int e4, int e) {
    int stride = gridDim.x * blockDim.x;
    int t0 = blockIdx.x * blockDim.x + threadIdx.x;
    const int4* d4 = (const int4*)dst;
    for (int i = t0; i < e4; i += stride) {
        int4 d = d4[i];
        atomicAdd(&g_cursor[d.x], 1);
        atomicAdd(&g_cursor[d.y], 1);
        atomicAdd(&g_cursor[d.z], 1);
        atomicAdd(&g_cursor[d.w], 1);
    }
    for (int i = e4 * 4 + t0; i < e; i += stride)
        atomicAdd(&g_cursor[dst[i]], 1);
}

__global__ void k_scan1(int n) {
    __shared__ int wsum[32];
    int tid = threadIdx.x, lane = tid & 31, w = tid >> 5;
    int i = blockIdx.x * 1024 + tid;
    int v = (i < n) ? g_cursor[i] : 0;
    int x = v;
    #pragma unroll
    for (int off = 1; off < 32; off <<= 1) {
        int t = __shfl_up_sync(0xffffffffu, x, off);
        if (lane >= off) x += t;
    }
    if (lane == 31) wsum[w] = x;
    __syncthreads();
    if (w == 0) {
        int s = wsum[lane];
        #pragma unroll
        for (int off = 1; off < 32; off <<= 1) {
            int t = __shfl_up_sync(0xffffffffu, s, off);
            if (lane >= off) s += t;
        }
        wsum[lane] = s;
    }
    __syncthreads();
    int incl = x + (w > 0 ? wsum[w - 1] : 0);
    if (i < n) g_rowptr[i] = incl - v;
    if (tid == 1023) g_bsum[blockIdx.x] = incl;
}

__global__ void k_scan2(int nb) {
    __shared__ int ws[4];
    int tid = threadIdx.x, lane = tid & 31, w = tid >> 5;
    int v = (tid < nb) ? g_bsum[tid] : 0;
    int x = v;
    #pragma unroll
    for (int off = 1; off < 32; off <<= 1) {
        int t = __shfl_up_sync(0xffffffffu, x, off);
        if (lane >= off) x += t;
    }
    if (lane == 31) ws[w] = x;
    __syncthreads();
    if (tid == 0) {
        int c = 0;
        #pragma unroll
        for (int k = 0; k < 4; k++) { int t = ws[k]; ws[k] = c; c += t; }
    }
    __syncthreads();
    if (tid < nb) g_bsum[tid] = x - v + ws[w];
}

__global__ void k_scan3(int n, int e) {
    int i = blockIdx.x * 1024 + threadIdx.x;
    if (i < n) {
        int v = g_rowptr[i] + g_bsum[blockIdx.x];
        g_rowptr[i] = v;
        g_cursor[i] = v;
    }
    if (i == 0) g_rowptr[n] = e;
}

__global__ void k_fill4(const int* __restrict__ src, const int* __restrict__ dst, int e4, int e) {
    int stride = gridDim.x * blockDim.x;
    int t0 = blockIdx.x * blockDim.x + threadIdx.x;
    const int4* s4 = (const int4*)src;
    const int4* d4 = (const int4*)dst;
    for (int i = t0; i < e4; i += stride) {
        int4 d = d4[i];
        int4 s = s4[i];
        int p0 = atomicAdd(&g_cursor[d.x], 1);
        int p1 = atomicAdd(&g_cursor[d.y], 1);
        int p2 = atomicAdd(&g_cursor[d.z], 1);
        int p3 = atomicAdd(&g_cursor[d.w], 1);
        g_col[p0] = s.x; g_col[p1] = s.y; g_col[p2] = s.z; g_col[p3] = s.w;
    }
    for (int i = e4 * 4 + t0; i < e; i += stride) {
        int p = atomicAdd(&g_cursor[dst[i]], 1);
        g_col[p] = src[i];
    }
}

__global__ void k_hist(const int* __restrict__ dst, int e) {
    int stride = gridDim.x * blockDim.x;
    for (int i = blockIdx.x * blockDim.x + threadIdx.x; i < e; i += stride)
        atomicAdd(&g_cursor[dst[i]], 1);
}
__global__ void k_fill(const int* __restrict__ src, const int* __restrict__ dst, int e) {
    int stride = gridDim.x * blockDim.x;
    for (int i = blockIdx.x * blockDim.x + threadIdx.x; i < e; i += stride) {
        int p = atomicAdd(&g_cursor[dst[i]], 1);
        g_col[p] = src[i];
    }
}

// ---------------- embedding lookup (also zeroes stats) -----------------------
__global__ void k_embed(const int* __restrict__ deg, const float* __restrict__ emb, int n) {
    if (blockIdx.x == 0 && threadIdx.x < 128) g_stats[threadIdx.x] = 0.f;
    int i = blockIdx.x * blockDim.x + threadIdx.x;
    if (i >= n * 32) return;
    int node = i >> 5, j = i & 31;
    float2 v = ((const float2*)emb)[deg[node] * 32 + j];
    ((float2*)g_z[0])[i] = v;
    g_zh[0][i] = pack_bf16x2(v);
}

// ---------------- fused GIN layer: smem-staged gather + dual GEMVs ------------
__global__ void __launch_bounds__(256) k_layer(
    const float* __restrict__ W1, const float* __restrict__ b1,
    const float* __restrict__ W2, const float* __restrict__ b2,
    const float* __restrict__ epsArr, int l, int n)
{
    __shared__ float4 sW1q[32][32];
    __shared__ float4 sW2q[32][32];
    __shared__ float2 sb1[32];
    __shared__ float2 sb2[32];
    __shared__ float4 sm4[8][2][16];
    __shared__ float4 sh4[8][2][16];
    __shared__ int    sidx[8][2][32];   // staged neighbor indices (per warp, per node)
    __shared__ float  bstat[128];

    int tid = threadIdx.x;
    {
        const float2* w1v = (const float2*)(W1 + l * 4096);
        const float2* w2v = (const float2*)(W2 + l * 4096);
        for (int i = tid; i < 1024; i += 256) {
            int k2 = i >> 5, c = i & 31;
            float2 a = w1v[(2 * k2) * 32 + c];
            float2 b = w1v[(2 * k2 + 1) * 32 + c];
            sW1q[k2][c] = make_float4(a.x, a.y, b.x, b.y);
            float2 a2 = w2v[(2 * k2) * 32 + c];
            float2 b2v = w2v[(2 * k2 + 1) * 32 + c];
            sW2q[k2][c] = make_float4(a2.x, a2.y, b2v.x, b2v.y);
        }
        if (tid < 32) {
            sb1[tid] = ((const float2*)(b1 + l * 64))[tid];
            sb2[tid] = ((const float2*)(b2 + l * 64))[tid];
        }
        if (tid < 128) bstat[tid] = 0.f;
    }
    __syncthreads();

    float ep = 1.0f + epsArr[l];
    const float2*       __restrict__ x2 = (const float2*)g_z[l];
    const unsigned int* __restrict__ xh = g_zh[l];
    float2* o2 = (float2*)g_z[l + 1];
    int w = tid >> 5, lane = tid & 31;
    float ssx = 0.f, ssy = 0.f, sqx = 0.f, sqy = 0.f;
    int gw = (blockIdx.x * 256 + tid) >> 5;
    int nw = (gridDim.x * 256) >> 5;

    for (int base = gw * 2; base < n; base += nw * 2) {
        int nA = base, nB = base + 1;
        bool hasB = (nB < n);

        int bA = g_rowptr[nA], reA = g_rowptr[nA + 1];
        int bB = hasB ? g_rowptr[nB] : 0, reB = hasB ? g_rowptr[nB + 1] : 0;
        float2 xvA = x2[nA * 32 + lane];
        float2 xvB = hasB ? x2[nB * 32 + lane] : make_float2(0.f, 0.f);
        float aA0x = ep * xvA.x, aA0y = ep * xvA.y, aA1x = 0.f, aA1y = 0.f;
        float aB0x = ep * xvB.x, aB0y = ep * xvB.y, aB1x = 0.f, aB1y = 0.f;

        const int4* iA4 = (const int4*)sidx[w][0];
        const int4* iB4 = (const int4*)sidx[w][1];

        // ------- interleaved dual-node gather, smem-staged indices -------
        while (bA + 32 <= reA && bB + 32 <= reB) {
            sidx[w][0][lane] = g_col[bA + lane];
            sidx[w][1][lane] = g_col[bB + lane];
            __syncwarp();
            #pragma unroll
            for (int q = 0; q < 8; q++) {
                int4 ja = iA4[q];
                int4 jb = iB4[q];
                unsigned int wA0 = xh[ja.x * 32 + lane];
                unsigned int wA1 = xh[ja.y * 32 + lane];
                unsigned int wB0 = xh[jb.x * 32 + lane];
                unsigned int wB1 = xh[jb.y * 32 + lane];
                unsigned int wA2 = xh[ja.z * 32 + lane];
                unsigned int wA3 = xh[ja.w * 32 + lane];
                unsigned int wB2 = xh[jb.z * 32 + lane];
                unsigned int wB3 = xh[jb.w * 32 + lane];
                aA0x += bf_lo(wA0); aA0y += bf_hi(wA0);
                aA1x += bf_lo(wA1); aA1y += bf_hi(wA1);
                aB0x += bf_lo(wB0); aB0y += bf_hi(wB0);
                aB1x += bf_lo(wB1); aB1y += bf_hi(wB1);
                aA0x += bf_lo(wA2); aA0y += bf_hi(wA2);
                aA1x += bf_lo(wA3); aA1y += bf_hi(wA3);
                aB0x += bf_lo(wB2); aB0y += bf_hi(wB2);
                aB1x += bf_lo(wB3); aB1y += bf_hi(wB3);
            }
            __syncwarp();
            bA += 32; bB += 32;
        }
        while (bA + 32 <= reA) {
            sidx[w][0][lane] = g_col[bA + lane];
            __syncwarp();
            #pragma unroll
            for (int q = 0; q < 8; q++) {
                int4 ja = iA4[q];
                unsigned int w0 = xh[ja.x * 32 + lane];
                unsigned int w1 = xh[ja.y * 32 + lane];
                unsigned int w2 = xh[ja.z * 32 + lane];
                unsigned int w3 = xh[ja.w * 32 + lane];
                aA0x += bf_lo(w0); aA0y += bf_hi(w0);
                aA1x += bf_lo(w1); aA1y += bf_hi(w1);
                aA0x += bf_lo(w2); aA0y += bf_hi(w2);
                aA1x += bf_lo(w3); aA1y += bf_hi(w3);
            }
            __syncwarp();
            bA += 32;
        }
        while (bB + 32 <= reB) {
            sidx[w][1][lane] = g_col[bB + lane];
            __syncwarp();
            #pragma unroll
            for (int q = 0; q < 8; q++) {
                int4 jb = iB4[q];
                unsigned int w0 = xh[jb.x * 32 + lane];
                unsigned int w1 = xh[jb.y * 32 + lane];
                unsigned int w2 = xh[jb.z * 32 + lane];
                unsigned int w3 = xh[jb.w * 32 + lane];
                aB0x += bf_lo(w0); aB0y += bf_hi(w0);
                aB1x += bf_lo(w1); aB1y += bf_hi(w1);
                aB0x += bf_lo(w2); aB0y += bf_hi(w2);
                aB1x += bf_lo(w3); aB1y += bf_hi(w3);
            }
            __syncwarp();
            bB += 32;
        }
        {   // staged tails (<32 each)
            int remA = reA - bA, remB = reB - bB;
            if (lane < remA) sidx[w][0][lane] = g_col[bA + lane];
            if (lane < remB) sidx[w][1][lane] = g_col[bB + lane];
            __syncwarp();
            int rem = remA > remB ? remA : remB;
            for (int t = 0; t < rem; t++) {
                if (t < remA) {
                    unsigned int wv = xh[sidx[w][0][t] * 32 + lane];
                    aA0x += bf_lo(wv); aA0y += bf_hi(wv);
                }
                if (t < remB) {
                    unsigned int wv = xh[sidx[w][1][t] * 32 + lane];
                    aB0x += bf_lo(wv); aB0y += bf_hi(wv);
                }
            }
            __syncwarp();
        }
        ((float2*)sm4[w][0])[lane] = make_float2(aA0x + aA1x, aA0y + aA1y);
        ((float2*)sm4[w][1])[lane] = make_float2(aB0x + aB1x, aB0y + aB1y);
        __syncwarp();

        // ------- dual GEMV1 (frozen R6 form) -------
        float2 hA = sb1[lane], hB = sb1[lane];
        const float4* mAv = (const float4*)sm4[w][0];
        const float4* mBv = (const float4*)sm4[w][1];
        #pragma unroll
        for (int kk = 0; kk < 16; kk++) {
            float4 m4A = mAv[kk];
            float4 m4B = mBv[kk];
            float4 w0 = sW1q[2 * kk][lane];
            float4 w1 = sW1q[2 * kk + 1][lane];
            hA.x = fmaf(m4A.x, w0.x, hA.x); hA.y = fmaf(m4A.x, w0.y, hA.y);
            hA.x = fmaf(m4A.y, w0.z, hA.x); hA.y = fmaf(m4A.y, w0.w, hA.y);
            hA.x = fmaf(m4A.z, w1.x, hA.x); hA.y = fmaf(m4A.z, w1.y, hA.y);
            hA.x = fmaf(m4A.w, w1.z, hA.x); hA.y = fmaf(m4A.w, w1.w, hA.y);
            hB.x = fmaf(m4B.x, w0.x, hB.x); hB.y = fmaf(m4B.x, w0.y, hB.y);
            hB.x = fmaf(m4B.y, w0.z, hB.x); hB.y = fmaf(m4B.y, w0.w, hB.y);
            hB.x = fmaf(m4B.z, w1.x, hB.x); hB.y = fmaf(m4B.z, w1.y, hB.y);
            hB.x = fmaf(m4B.w, w1.z, hB.x); hB.y = fmaf(m4B.w, w1.w, hB.y);
        }
        hA.x = lrelu(hA.x); hA.y = lrelu(hA.y);
        hB.x = lrelu(hB.x); hB.y = lrelu(hB.y);
        ((float2*)sh4[w][0])[lane] = hA;
        ((float2*)sh4[w][1])[lane] = hB;
        __syncwarp();

        // ------- dual GEMV2 (frozen R6 form) -------
        float2 oA = sb2[lane], oB = sb2[lane];
        const float4* hAv = (const float4*)sh4[w][0];
        const float4* hBv = (const float4*)sh4[w][1];
        #pragma unroll
        for (int kk = 0; kk < 16; kk++) {
            float4 m4A = hAv[kk];
            float4 m4B = hBv[kk];
            float4 w0 = sW2q[2 * kk][lane];
            float4 w1 = sW2q[2 * kk + 1][lane];
            oA.x = fmaf(m4A.x, w0.x, oA.x); oA.y = fmaf(m4A.x, w0.y, oA.y);
            oA.x = fmaf(m4A.y, w0.z, oA.x); oA.y = fmaf(m4A.y, w0.w, oA.y);
            oA.x = fmaf(m4A.z, w1.x, oA.x); oA.y = fmaf(m4A.z, w1.y, oA.y);
            oA.x = fmaf(m4A.w, w1.z, oA.x); oA.y = fmaf(m4A.w, w1.w, oA.y);
            oB.x = fmaf(m4B.x, w0.x, oB.x); oB.y = fmaf(m4B.x, w0.y, oB.y);
            oB.x = fmaf(m4B.y, w0.z, oB.x); oB.y = fmaf(m4B.y, w0.w, oB.y);
            oB.x = fmaf(m4B.z, w1.x, oB.x); oB.y = fmaf(m4B.z, w1.y, oB.y);
            oB.x = fmaf(m4B.w, w1.z, oB.x); oB.y = fmaf(m4B.w, w1.w, oB.y);
        }
        o2[nA * 32 + lane] = oA;
        ssx += oA.x; ssy += oA.y; sqx += oA.x * oA.x; sqy += oA.y * oA.y;
        if (hasB) {
            o2[nB * 32 + lane] = oB;
            ssx += oB.x; ssy += oB.y; sqx += oB.x * oB.x; sqy += oB.y * oB.y;
        }
        __syncwarp();
    }

    atomicAdd(&bstat[2 * lane], ssx);
    atomicAdd(&bstat[2 * lane + 1], ssy);
    atomicAdd(&bstat[64 + 2 * lane], sqx);
    atomicAdd(&bstat[64 + 2 * lane + 1], sqy);
    __syncthreads();
    if (tid < 128) atomicAdd(&g_stats[tid], bstat[tid]);
}

// ---------------- BN params (reads stats, then re-zeroes them) ----------------
__global__ void k_bnparams(const float* __restrict__ g, const float* __restrict__ b, int n) {
    int i = threadIdx.x;
    if (i < 64) {
        float inv = 1.0f / (float)n;
        float mean = g_stats[i] * inv;
        float var = g_stats[64 + i] * inv - mean * mean;
        float sc = g[i] * rsqrtf(var + 1e-5f);
        g_stats[128 + i] = sc;
        g_stats[192 + i] = b[i] - sc * mean;
        g_stats[i] = 0.f;
        g_stats[64 + i] = 0.f;
    }
}

// ---------------- BN + leaky (fp32 in-place + bf16 copy) ----------------------
__global__ void k_bnapply(int lz, int n) {
    int i = blockIdx.x * blockDim.x + threadIdx.x;
    if (i >= n * 32) return;
    int c = (i & 31) * 2;
    float2* z2 = (float2*)g_z[lz];
    float2 v = z2[i];
    v.x = lrelu(g_stats[128 + c] * v.x + g_stats[192 + c]);
    v.y = lrelu(g_stats[128 + c + 1] * v.y + g_stats[192 + c + 1]);
    z2[i] = v;
    g_zh[lz][i] = pack_bf16x2(v);
}

// ---------------- FC layer 1 (two 128-row chunks, dual-node, frozen R6) -------
__global__ void __launch_bounds__(256) k_fc(
    const float* __restrict__ fcW1, const float* __restrict__ fcb1, int chunk, int n)
{
    __shared__ float4 sWq[64][32];
    __shared__ float4 sx4[8][2][32];
    __shared__ float2 sb[32];
    __shared__ float  bstat[128];
    int tid = threadIdx.x;
    {
        const float2* wv = (const float2*)(fcW1 + chunk * 128 * 64);
        for (int i = tid; i < 2048; i += 256) {
            int k2 = i >> 5, c = i & 31;
            float2 a = wv[(2 * k2) * 32 + c];
            float2 b = wv[(2 * k2 + 1) * 32 + c];
            sWq[k2][c] = make_float4(a.x, a.y, b.x, b.y);
        }
        if (tid < 32) sb[tid] = (chunk == 0) ? ((const float2*)fcb1)[tid] : make_float2(0.f, 0.f);
        if (tid < 128) bstat[tid] = 0.f;
    }
    __syncthreads();

    const float2* za = (const float2*)g_z[2 * chunk];
    const float2* zb = (const float2*)g_z[2 * chunk + 1];
    float2* u2 = (float2*)g_u;
    int w = tid >> 5, lane = tid & 31;
    float ssx = 0.f, ssy = 0.f, sqx = 0.f, sqy = 0.f;
    int gw = (blockIdx.x * 256 + tid) >> 5;
    int nw = (gridDim.x * 256) >> 5;

    for (int base = gw * 2; base < n; base += nw * 2) {
        int nA = base, nB = base + 1;
        bool hasB = (nB < n);
        ((float2*)sx4[w][0])[lane]      = za[nA * 32 + lane];
        ((float2*)sx4[w][0])[32 + lane] = zb[nA * 32 + lane];
        if (hasB) {
            ((float2*)sx4[w][1])[lane]      = za[nB * 32 + lane];
            ((float2*)sx4[w][1])[32 + lane] = zb[nB * 32 + lane];
        }
        __syncwarp();

        float2 uA = (chunk == 0) ? sb[lane] : u2[nA * 32 + lane];
        float2 uB = (chunk == 0) ? sb[lane] : (hasB ? u2[nB * 32 + lane] : make_float2(0.f, 0.f));
        const float4* xAv = (const float4*)sx4[w][0];
        const float4* xBv = (const float4*)sx4[w][1];
        #pragma unroll
        for (int kk = 0; kk < 32; kk++) {
            float4 m4A = xAv[kk];
            float4 m4B = xBv[kk];
            float4 w0 = sWq[2 * kk][lane];
            float4 w1 = sWq[2 * kk + 1][lane];
            uA.x = fmaf(m4A.x, w0.x, uA.x); uA.y = fmaf(m4A.x, w0.y, uA.y);
            uA.x = fmaf(m4A.y, w0.z, uA.x); uA.y = fmaf(m4A.y, w0.w, uA.y);
            uA.x = fmaf(m4A.z, w1.x, uA.x); uA.y = fmaf(m4A.z, w1.y, uA.y);
            uA.x = fmaf(m4A.w, w1.z, uA.x); uA.y = fmaf(m4A.w, w1.w, uA.y);
            uB.x = fmaf(m4B.x, w0.x, uB.x); uB.y = fmaf(m4B.x, w0.y, uB.y);
            uB.x = fmaf(m4B.y, w0.z, uB.x); uB.y = fmaf(m4B.y, w0.w, uB.y);
            uB.x = fmaf(m4B.z, w1.x, uB.x); uB.y = fmaf(m4B.z, w1.y, uB.y);
            uB.x = fmaf(m4B.w, w1.z, uB.x); uB.y = fmaf(m4B.w, w1.w, uB.y);
        }
        u2[nA * 32 + lane] = uA;
        if (chunk == 1) { ssx += uA.x; ssy += uA.y; sqx += uA.x * uA.x; sqy += uA.y * uA.y; }
        if (hasB) {
            u2[nB * 32 + lane] = uB;
            if (chunk == 1) { ssx += uB.x; ssy += uB.y; sqx += uB.x * uB.x; sqy += uB.y * uB.y; }
        }
        __syncwarp();
    }

    if (chunk == 1) {
        atomicAdd(&bstat[2 * lane], ssx);
        atomicAdd(&bstat[2 * lane + 1], ssy);
        atomicAdd(&bstat[64 + 2 * lane], sqx);
        atomicAdd(&bstat[64 + 2 * lane + 1], sqy);
        __syncthreads();
        if (tid < 128) atomicAdd(&g_stats[tid], bstat[tid]);
    }
}

// ---------------- head --------------------------------------------------------
__global__ void k_head(const float* __restrict__ fcW2, const float* __restrict__ fcb2,
                       float* __restrict__ out, int n) {
    int gt = blockIdx.x * blockDim.x + threadIdx.x;
    int node = gt >> 5, lane = gt & 31;
    if (node >= n) return;
    float2 u = ((const float2*)g_u)[node * 32 + lane];
    int c = 2 * lane;
    float y0 = lrelu(g_stats[128 + c] * u.x + g_stats[192 + c]);
    float y1 = lrelu(g_stats[128 + c + 1] * u.y + g_stats[192 + c + 1]);
    float p = y0 * fcW2[c] + y1 * fcW2[c + 1];
    #pragma unroll
    for (int o = 16; o > 0; o >>= 1) p += __shfl_xor_sync(0xffffffffu, p, o);
    if (lane == 0) out[node] = 1.0f / (1.0f + expf(-(p + fcb2[0])));
}

// ---------------- launch -------------------------------------------------------
extern "C" void kernel_launch(void* const* d_in, const int* in_sizes, int n_in,
                              void* d_out, int out_size) {
    const int*   node_deg = (const int*)d_in[0];
    const int*   edge_idx = (const int*)d_in[1];
    const float* embed    = (const float*)d_in[2];
    const float* eps      = (const float*)d_in[3];
    const float* W1       = (const float*)d_in[4];
    const float* b1       = (const float*)d_in[5];
    const float* W2       = (const float*)d_in[6];
    const float* b2       = (const float*)d_in[7];
    const float* bn_g     = (const float*)d_in[8];
    const float* bn_b     = (const float*)d_in[9];
    const float* fcW1     = (const float*)d_in[10];
    const float* fcb1     = (const float*)d_in[11];
    const float* fc_bn_g  = (const float*)d_in[12];
    const float* fc_bn_b  = (const float*)d_in[13];
    const float* fcW2     = (const float*)d_in[14];
    const float* fcb2     = (const float*)d_in[15];

    int n = in_sizes[0];
    int e = in_sizes[1] / 2;
    const int* src = edge_idx;
    const int* dst = edge_idx + e;

    int elemBlocks = (n * 32 + 255) / 256;
    int nb = (n + 1023) / 1024;
    const int PGRID = 592;

    bool vec4 = ((e & 3) == 0)
             && ((((unsigned long long)(size_t)src) & 15ull) == 0)
             && ((((unsigned long long)(size_t)dst) & 15ull) == 0);

    k_zero_deg<<<(n + 255) / 256, 256>>>(n);
    if (vec4) k_hist4<<<1024, 256>>>(dst, e / 4, e);
    else      k_hist<<<1024, 256>>>(dst, e);
    k_scan1<<<nb, 1024>>>(n);
    k_scan2<<<1, 128>>>(nb);
    k_scan3<<<nb, 1024>>>(n, e);
    if (vec4) k_fill4<<<1024, 256>>>(src, dst, e / 4, e);
    else      k_fill<<<1024, 256>>>(src, dst, e);

    k_embed<<<elemBlocks, 256>>>(node_deg, embed, n);

    for (int l = 0; l < 3; l++) {
        k_layer<<<PGRID, 256>>>(W1, b1, W2, b2, eps, l, n);
        k_bnparams<<<1, 64>>>(bn_g + l * 64, bn_b + l * 64, n);
        k_bnapply<<<elemBlocks, 256>>>(l + 1, n);
    }

    k_fc<<<PGRID, 256>>>(fcW1, fcb1, 0, n);
    k_fc<<<PGRID, 256>>>(fcW1, fcb1, 1, n);
    k_bnparams<<<1, 64>>>(fc_bn_g, fc_bn_b, n);
    k_head<<<elemBlocks, 256>>>(fcW2, fcb2, (float*)d_out, n);
}

// round 12
// speedup vs baseline: 1.5723x; 1.0027x over previous
#include <cuda_runtime.h>
#include <cuda_bf16.h>
#include <stdint.h>
#include <math.h>

#define MAXN 100000
#define MAXE 3200000

// ---------------- scratch (static device globals) ---------------------------
__device__ int          g_cursor[MAXN];
__device__ int          g_rowptr[MAXN + 1];
__device__ int          g_col[MAXE];
__device__ int          g_bsum[256];
__device__ float        g_z[4][MAXN * 64];     // fp32 master copies z0..z3
__device__ unsigned int g_zh[4][MAXN * 32];    // bf16x2 gather copies
__device__ float        g_u[MAXN * 64];
__device__ float        g_statsA[4][128];      // per-layer sums: [slot][0:64)=sum, [64:128)=sumsq

__device__ __forceinline__ float lrelu(float x) { return x >= 0.f ? x : 0.01f * x; }

__device__ __forceinline__ unsigned int pack_bf16x2(float2 v) {
    __nv_bfloat162 b = __float22bfloat162_rn(v);
    return *(unsigned int*)&b;
}
__device__ __forceinline__ float bf_lo(unsigned int w) { return __int_as_float((int)(w << 16)); }
__device__ __forceinline__ float bf_hi(unsigned int w) { return __int_as_float((int)(w & 0xffff0000u)); }

// ---------------- CSR build --------------------------------------------------
__global__ void k_hist4(const int* __restrict__ dst, int e4, int e) {
    int stride = gridDim.x * blockDim.x;
    int t0 = blockIdx.x * blockDim.x + threadIdx.x;
    const int4* d4 = (const int4*)dst;
    for (int i = t0; i < e4; i += stride) {
        int4 d = d4[i];
        atomicAdd(&g_cursor[d.x], 1);
        atomicAdd(&g_cursor[d.y], 1);
        atomicAdd(&g_cursor[d.z], 1);
        atomicAdd(&g_cursor[d.w], 1);
    }
    for (int i = e4 * 4 + t0; i < e; i += stride)
        atomicAdd(&g_cursor[dst[i]], 1);
}

__global__ void k_scan1(int n) {
    __shared__ int wsum[32];
    int tid = threadIdx.x, lane = tid & 31, w = tid >> 5;
    int i = blockIdx.x * 1024 + tid;
    int v = (i < n) ? g_cursor[i] : 0;
    int x = v;
    #pragma unroll
    for (int off = 1; off < 32; off <<= 1) {
        int t = __shfl_up_sync(0xffffffffu, x, off);
        if (lane >= off) x += t;
    }
    if (lane == 31) wsum[w] = x;
    __syncthreads();
    if (w == 0) {
        int s = wsum[lane];
        #pragma unroll
        for (int off = 1; off < 32; off <<= 1) {
            int t = __shfl_up_sync(0xffffffffu, s, off);
            if (lane >= off) s += t;
        }
        wsum[lane] = s;
    }
    __syncthreads();
    int incl = x + (w > 0 ? wsum[w - 1] : 0);
    if (i < n) g_rowptr[i] = incl - v;
    if (tid == 1023) g_bsum[blockIdx.x] = incl;
}

__global__ void k_scan2(int nb) {
    __shared__ int ws[4];
    int tid = threadIdx.x, lane = tid & 31, w = tid >> 5;
    int v = (tid < nb) ? g_bsum[tid] : 0;
    int x = v;
    #pragma unroll
    for (int off = 1; off < 32; off <<= 1) {
        int t = __shfl_up_sync(0xffffffffu, x, off);
        if (lane >= off) x += t;
    }
    if (lane == 31) ws[w] = x;
    __syncthreads();
    if (tid == 0) {
        int c = 0;
        #pragma unroll
        for (int k = 0; k < 4; k++) { int t = ws[k]; ws[k] = c; c += t; }
    }
    __syncthreads();
    if (tid < nb) g_bsum[tid] = x - v + ws[w];
}

__global__ void k_scan3(int n, int e) {
    int i = blockIdx.x * 1024 + threadIdx.x;
    if (i < n) {
        int v = g_rowptr[i] + g_bsum[blockIdx.x];
        g_rowptr[i] = v;
        g_cursor[i] = v;
    }
    if (i == 0) g_rowptr[n] = e;
}

__global__ void k_fill4(const int* __restrict__ src, const int* __restrict__ dst, int e4, int e) {
    int stride = gridDim.x * blockDim.x;
    int t0 = blockIdx.x * blockDim.x + threadIdx.x;
    const int4* s4 = (const int4*)src;
    const int4* d4 = (const int4*)dst;
    for (int i = t0; i < e4; i += stride) {
        int4 d = d4[i];
        int4 s = s4[i];
        int p0 = atomicAdd(&g_cursor[d.x], 1);
        int p1 = atomicAdd(&g_cursor[d.y], 1);
        int p2 = atomicAdd(&g_cursor[d.z], 1);
        int p3 = atomicAdd(&g_cursor[d.w], 1);
        g_col[p0] = s.x; g_col[p1] = s.y; g_col[p2] = s.z; g_col[p3] = s.w;
    }
    for (int i = e4 * 4 + t0; i < e; i += stride) {
        int p = atomicAdd(&g_cursor[dst[i]], 1);
        g_col[p] = src[i];
    }
}

__global__ void k_hist(const int* __restrict__ dst, int e) {
    int stride = gridDim.x * blockDim.x;
    for (int i = blockIdx.x * blockDim.x + threadIdx.x; i < e; i += stride)
        atomicAdd(&g_cursor[dst[i]], 1);
}
__global__ void k_fill(const int* __restrict__ src, const int* __restrict__ dst, int e) {
    int stride = gridDim.x * blockDim.x;
    for (int i = blockIdx.x * blockDim.x + threadIdx.x; i < e; i += stride) {
        int p = atomicAdd(&g_cursor[dst[i]], 1);
        g_col[p] = src[i];
    }
}

// ---------------- embedding lookup (also zeroes cursor + all stats slots) ----
__global__ void k_embed(const int* __restrict__ deg, const float* __restrict__ emb, int n) {
    int i = blockIdx.x * blockDim.x + threadIdx.x;
    if (i < 512) ((float*)g_statsA)[i] = 0.f;
    if (i < n) g_cursor[i] = 0;
    if (i >= n * 32) return;
    int node = i >> 5, j = i & 31;
    float2 v = ((const float2*)emb)[deg[node] * 32 + j];
    ((float2*)g_z[0])[i] = v;
    g_zh[0][i] = pack_bf16x2(v);
}

// ---------------- fused GIN layer: smem-staged gather + dual GEMVs ------------
__global__ void __launch_bounds__(256) k_layer(
    const float* __restrict__ W1, const float* __restrict__ b1,
    const float* __restrict__ W2, const float* __restrict__ b2,
    const float* __restrict__ epsArr, int l, int n)
{
    __shared__ float4 sW1q[32][32];
    __shared__ float4 sW2q[32][32];
    __shared__ float2 sb1[32];
    __shared__ float2 sb2[32];
    __shared__ float4 sm4[8][2][16];
    __shared__ float4 sh4[8][2][16];
    __shared__ int    sidx[8][2][32];
    __shared__ float  bstat[128];

    int tid = threadIdx.x;
    {
        const float2* w1v = (const float2*)(W1 + l * 4096);
        const float2* w2v = (const float2*)(W2 + l * 4096);
        for (int i = tid; i < 1024; i += 256) {
            int k2 = i >> 5, c = i & 31;
            float2 a = w1v[(2 * k2) * 32 + c];
            float2 b = w1v[(2 * k2 + 1) * 32 + c];
            sW1q[k2][c] = make_float4(a.x, a.y, b.x, b.y);
            float2 a2 = w2v[(2 * k2) * 32 + c];
            float2 b2v = w2v[(2 * k2 + 1) * 32 + c];
            sW2q[k2][c] = make_float4(a2.x, a2.y, b2v.x, b2v.y);
        }
        if (tid < 32) {
            sb1[tid] = ((const float2*)(b1 + l * 64))[tid];
            sb2[tid] = ((const float2*)(b2 + l * 64))[tid];
        }
        if (tid < 128) bstat[tid] = 0.f;
    }
    __syncthreads();

    float ep = 1.0f + epsArr[l];
    const float2*       __restrict__ x2 = (const float2*)g_z[l];
    const unsigned int* __restrict__ xh = g_zh[l];
    float2* o2 = (float2*)g_z[l + 1];
    int w = tid >> 5, lane = tid & 31;
    float ssx = 0.f, ssy = 0.f, sqx = 0.f, sqy = 0.f;
    int gw = (blockIdx.x * 256 + tid) >> 5;
    int nw = (gridDim.x * 256) >> 5;

    for (int base = gw * 2; base < n; base += nw * 2) {
        int nA = base, nB = base + 1;
        bool hasB = (nB < n);

        int bA = g_rowptr[nA], reA = g_rowptr[nA + 1];
        int bB = hasB ? g_rowptr[nB] : 0, reB = hasB ? g_rowptr[nB + 1] : 0;
        float2 xvA = x2[nA * 32 + lane];
        float2 xvB = hasB ? x2[nB * 32 + lane] : make_float2(0.f, 0.f);
        float aA0x = ep * xvA.x, aA0y = ep * xvA.y, aA1x = 0.f, aA1y = 0.f;
        float aB0x = ep * xvB.x, aB0y = ep * xvB.y, aB1x = 0.f, aB1y = 0.f;

        const int4* iA4 = (const int4*)sidx[w][0];
        const int4* iB4 = (const int4*)sidx[w][1];

        while (bA + 32 <= reA && bB + 32 <= reB) {
            sidx[w][0][lane] = g_col[bA + lane];
            sidx[w][1][lane] = g_col[bB + lane];
            __syncwarp();
            #pragma unroll
            for (int q = 0; q < 8; q++) {
                int4 ja = iA4[q];
                int4 jb = iB4[q];
                unsigned int wA0 = xh[ja.x * 32 + lane];
                unsigned int wA1 = xh[ja.y * 32 + lane];
                unsigned int wB0 = xh[jb.x * 32 + lane];
                unsigned int wB1 = xh[jb.y * 32 + lane];
                unsigned int wA2 = xh[ja.z * 32 + lane];
                unsigned int wA3 = xh[ja.w * 32 + lane];
                unsigned int wB2 = xh[jb.z * 32 + lane];
                unsigned int wB3 = xh[jb.w * 32 + lane];
                aA0x += bf_lo(wA0); aA0y += bf_hi(wA0);
                aA1x += bf_lo(wA1); aA1y += bf_hi(wA1);
                aB0x += bf_lo(wB0); aB0y += bf_hi(wB0);
                aB1x += bf_lo(wB1); aB1y += bf_hi(wB1);
                aA0x += bf_lo(wA2); aA0y += bf_hi(wA2);
                aA1x += bf_lo(wA3); aA1y += bf_hi(wA3);
                aB0x += bf_lo(wB2); aB0y += bf_hi(wB2);
                aB1x += bf_lo(wB3); aB1y += bf_hi(wB3);
            }
            __syncwarp();
            bA += 32; bB += 32;
        }
        while (bA + 32 <= reA) {
            sidx[w][0][lane] = g_col[bA + lane];
            __syncwarp();
            #pragma unroll
            for (int q = 0; q < 8; q++) {
                int4 ja = iA4[q];
                unsigned int w0 = xh[ja.x * 32 + lane];
                unsigned int w1 = xh[ja.y * 32 + lane];
                unsigned int w2 = xh[ja.z * 32 + lane];
                unsigned int w3 = xh[ja.w * 32 + lane];
                aA0x += bf_lo(w0); aA0y += bf_hi(w0);
                aA1x += bf_lo(w1); aA1y += bf_hi(w1);
                aA0x += bf_lo(w2); aA0y += bf_hi(w2);
                aA1x += bf_lo(w3); aA1y += bf_hi(w3);
            }
            __syncwarp();
            bA += 32;
        }
        while (bB + 32 <= reB) {
            sidx[w][1][lane] = g_col[bB + lane];
            __syncwarp();
            #pragma unroll
            for (int q = 0; q < 8; q++) {
                int4 jb = iB4[q];
                unsigned int w0 = xh[jb.x * 32 + lane];
                unsigned int w1 = xh[jb.y * 32 + lane];
                unsigned int w2 = xh[jb.z * 32 + lane];
                unsigned int w3 = xh[jb.w * 32 + lane];
                aB0x += bf_lo(w0); aB0y += bf_hi(w0);
                aB1x += bf_lo(w1); aB1y += bf_hi(w1);
                aB0x += bf_lo(w2); aB0y += bf_hi(w2);
                aB1x += bf_lo(w3); aB1y += bf_hi(w3);
            }
            __syncwarp();
            bB += 32;
        }
        {
            int remA = reA - bA, remB = reB - bB;
            if (lane < remA) sidx[w][0][lane] = g_col[bA + lane];
            if (lane < remB) sidx[w][1][lane] = g_col[bB + lane];
            __syncwarp();
            int rem = remA > remB ? remA : remB;
            for (int t = 0; t < rem; t++) {
                if (t < remA) {
                    unsigned int wv = xh[sidx[w][0][t] * 32 + lane];
                    aA0x += bf_lo(wv); aA0y += bf_hi(wv);
                }
                if (t < remB) {
                    unsigned int wv = xh[sidx[w][1][t] * 32 + lane];
                    aB0x += bf_lo(wv); aB0y += bf_hi(wv);
                }
            }
            __syncwarp();
        }
        ((float2*)sm4[w][0])[lane] = make_float2(aA0x + aA1x, aA0y + aA1y);
        ((float2*)sm4[w][1])[lane] = make_float2(aB0x + aB1x, aB0y + aB1y);
        __syncwarp();

        // ------- dual GEMV1 (frozen) -------
        float2 hA = sb1[lane], hB = sb1[lane];
        const float4* mAv = (const float4*)sm4[w][0];
        const float4* mBv = (const float4*)sm4[w][1];
        #pragma unroll
        for (int kk = 0; kk < 16; kk++) {
            float4 m4A = mAv[kk];
            float4 m4B = mBv[kk];
            float4 w0 = sW1q[2 * kk][lane];
            float4 w1 = sW1q[2 * kk + 1][lane];
            hA.x = fmaf(m4A.x, w0.x, hA.x); hA.y = fmaf(m4A.x, w0.y, hA.y);
            hA.x = fmaf(m4A.y, w0.z, hA.x); hA.y = fmaf(m4A.y, w0.w, hA.y);
            hA.x = fmaf(m4A.z, w1.x, hA.x); hA.y = fmaf(m4A.z, w1.y, hA.y);
            hA.x = fmaf(m4A.w, w1.z, hA.x); hA.y = fmaf(m4A.w, w1.w, hA.y);
            hB.x = fmaf(m4B.x, w0.x, hB.x); hB.y = fmaf(m4B.x, w0.y, hB.y);
            hB.x = fmaf(m4B.y, w0.z, hB.x); hB.y = fmaf(m4B.y, w0.w, hB.y);
            hB.x = fmaf(m4B.z, w1.x, hB.x); hB.y = fmaf(m4B.z, w1.y, hB.y);
            hB.x = fmaf(m4B.w, w1.z, hB.x); hB.y = fmaf(m4B.w, w1.w, hB.y);
        }
        hA.x = lrelu(hA.x); hA.y = lrelu(hA.y);
        hB.x = lrelu(hB.x); hB.y = lrelu(hB.y);
        ((float2*)sh4[w][0])[lane] = hA;
        ((float2*)sh4[w][1])[lane] = hB;
        __syncwarp();

        // ------- dual GEMV2 (frozen) -------
        float2 oA = sb2[lane], oB = sb2[lane];
        const float4* hAv = (const float4*)sh4[w][0];
        const float4* hBv = (const float4*)sh4[w][1];
        #pragma unroll
        for (int kk = 0; kk < 16; kk++) {
            float4 m4A = hAv[kk];
            float4 m4B = hBv[kk];
            float4 w0 = sW2q[2 * kk][lane];
            float4 w1 = sW2q[2 * kk + 1][lane];
            oA.x = fmaf(m4A.x, w0.x, oA.x); oA.y = fmaf(m4A.x, w0.y, oA.y);
            oA.x = fmaf(m4A.y, w0.z, oA.x); oA.y = fmaf(m4A.y, w0.w, oA.y);
            oA.x = fmaf(m4A.z, w1.x, oA.x); oA.y = fmaf(m4A.z, w1.y, oA.y);
            oA.x = fmaf(m4A.w, w1.z, oA.x); oA.y = fmaf(m4A.w, w1.w, oA.y);
            oB.x = fmaf(m4B.x, w0.x, oB.x); oB.y = fmaf(m4B.x, w0.y, oB.y);
            oB.x = fmaf(m4B.y, w0.z, oB.x); oB.y = fmaf(m4B.y, w0.w, oB.y);
            oB.x = fmaf(m4B.z, w1.x, oB.x); oB.y = fmaf(m4B.z, w1.y, oB.y);
            oB.x = fmaf(m4B.w, w1.z, oB.x); oB.y = fmaf(m4B.w, w1.w, oB.y);
        }
        o2[nA * 32 + lane] = oA;
        ssx += oA.x; ssy += oA.y; sqx += oA.x * oA.x; sqy += oA.y * oA.y;
        if (hasB) {
            o2[nB * 32 + lane] = oB;
            ssx += oB.x; ssy += oB.y; sqx += oB.x * oB.x; sqy += oB.y * oB.y;
        }
        __syncwarp();
    }

    atomicAdd(&bstat[2 * lane], ssx);
    atomicAdd(&bstat[2 * lane + 1], ssy);
    atomicAdd(&bstat[64 + 2 * lane], sqx);
    atomicAdd(&bstat[64 + 2 * lane + 1], sqy);
    __syncthreads();
    if (tid < 128) atomicAdd(&g_statsA[l][tid], bstat[tid]);
}

// ---------------- BN + leaky (params computed per-block in smem) ---------------
__global__ void k_bnapply(const float* __restrict__ g, const float* __restrict__ b,
                          int lz, int n) {
    __shared__ float ssc[64];
    __shared__ float ssh[64];
    int tid = threadIdx.x;
    int slot = lz - 1;
    if (tid < 64) {
        float inv = 1.0f / (float)n;
        float mean = g_statsA[slot][tid] * inv;
        float var = g_statsA[slot][64 + tid] * inv - mean * mean;
        float sc = g[tid] * rsqrtf(var + 1e-5f);
        ssc[tid] = sc;
        ssh[tid] = b[tid] - sc * mean;
    }
    __syncthreads();
    int i = blockIdx.x * blockDim.x + tid;
    if (i >= n * 32) return;
    int c = (i & 31) * 2;
    float2* z2 = (float2*)g_z[lz];
    float2 v = z2[i];
    v.x = lrelu(ssc[c] * v.x + ssh[c]);
    v.y = lrelu(ssc[c + 1] * v.y + ssh[c + 1]);
    z2[i] = v;
    g_zh[lz][i] = pack_bf16x2(v);
}

// ---------------- FC layer 1 (two 128-row chunks, dual-node, frozen) ----------
__global__ void __launch_bounds__(256) k_fc(
    const float* __restrict__ fcW1, const float* __restrict__ fcb1, int chunk, int n)
{
    __shared__ float4 sWq[64][32];
    __shared__ float4 sx4[8][2][32];
    __shared__ float2 sb[32];
    __shared__ float  bstat[128];
    int tid = threadIdx.x;
    {
        const float2* wv = (const float2*)(fcW1 + chunk * 128 * 64);
        for (int i = tid; i < 2048; i += 256) {
            int k2 = i >> 5, c = i & 31;
            float2 a = wv[(2 * k2) * 32 + c];
            float2 b = wv[(2 * k2 + 1) * 32 + c];
            sWq[k2][c] = make_float4(a.x, a.y, b.x, b.y);
        }
        if (tid < 32) sb[tid] = (chunk == 0) ? ((const float2*)fcb1)[tid] : make_float2(0.f, 0.f);
        if (tid < 128) bstat[tid] = 0.f;
    }
    __syncthreads();

    const float2* za = (const float2*)g_z[2 * chunk];
    const float2* zb = (const float2*)g_z[2 * chunk + 1];
    float2* u2 = (float2*)g_u;
    int w = tid >> 5, lane = tid & 31;
    float ssx = 0.f, ssy = 0.f, sqx = 0.f, sqy = 0.f;
    int gw = (blockIdx.x * 256 + tid) >> 5;
    int nw = (gridDim.x * 256) >> 5;

    for (int base = gw * 2; base < n; base += nw * 2) {
        int nA = base, nB = base + 1;
        bool hasB = (nB < n);
        ((float2*)sx4[w][0])[lane]      = za[nA * 32 + lane];
        ((float2*)sx4[w][0])[32 + lane] = zb[nA * 32 + lane];
        if (hasB) {
            ((float2*)sx4[w][1])[lane]      = za[nB * 32 + lane];
            ((float2*)sx4[w][1])[32 + lane] = zb[nB * 32 + lane];
        }
        __syncwarp();

        float2 uA = (chunk == 0) ? sb[lane] : u2[nA * 32 + lane];
        float2 uB = (chunk == 0) ? sb[lane] : (hasB ? u2[nB * 32 + lane] : make_float2(0.f, 0.f));
        const float4* xAv = (const float4*)sx4[w][0];
        const float4* xBv = (const float4*)sx4[w][1];
        #pragma unroll
        for (int kk = 0; kk < 32; kk++) {
            float4 m4A = xAv[kk];
            float4 m4B = xBv[kk];
            float4 w0 = sWq[2 * kk][lane];
            float4 w1 = sWq[2 * kk + 1][lane];
            uA.x = fmaf(m4A.x, w0.x, uA.x); uA.y = fmaf(m4A.x, w0.y, uA.y);
            uA.x = fmaf(m4A.y, w0.z, uA.x); uA.y = fmaf(m4A.y, w0.w, uA.y);
            uA.x = fmaf(m4A.z, w1.x, uA.x); uA.y = fmaf(m4A.z, w1.y, uA.y);
            uA.x = fmaf(m4A.w, w1.z, uA.x); uA.y = fmaf(m4A.w, w1.w, uA.y);
            uB.x = fmaf(m4B.x, w0.x, uB.x); uB.y = fmaf(m4B.x, w0.y, uB.y);
            uB.x = fmaf(m4B.y, w0.z, uB.x); uB.y = fmaf(m4B.y, w0.w, uB.y);
            uB.x = fmaf(m4B.z, w1.x, uB.x); uB.y = fmaf(m4B.z, w1.y, uB.y);
            uB.x = fmaf(m4B.w, w1.z, uB.x); uB.y = fmaf(m4B.w, w1.w, uB.y);
        }
        u2[nA * 32 + lane] = uA;
        if (chunk == 1) { ssx += uA.x; ssy += uA.y; sqx += uA.x * uA.x; sqy += uA.y * uA.y; }
        if (hasB) {
            u2[nB * 32 + lane] = uB;
            if (chunk == 1) { ssx += uB.x; ssy += uB.y; sqx += uB.x * uB.x; sqy += uB.y * uB.y; }
        }
        __syncwarp();
    }

    if (chunk == 1) {
        atomicAdd(&bstat[2 * lane], ssx);
        atomicAdd(&bstat[2 * lane + 1], ssy);
        atomicAdd(&bstat[64 + 2 * lane], sqx);
        atomicAdd(&bstat[64 + 2 * lane + 1], sqy);
        __syncthreads();
        if (tid < 128) atomicAdd(&g_statsA[3][tid], bstat[tid]);
    }
}

// ---------------- head: params in smem + BN + leaky + dot + sigmoid -----------
__global__ void k_head(const float* __restrict__ g, const float* __restrict__ b,
                       const float* __restrict__ fcW2, const float* __restrict__ fcb2,
                       float* __restrict__ out, int n) {
    __shared__ float ssc[64];
    __shared__ float ssh[64];
    int tid = threadIdx.x;
    if (tid < 64) {
        float inv = 1.0f / (float)n;
        float mean = g_statsA[3][tid] * inv;
        float var = g_statsA[3][64 + tid] * inv - mean * mean;
        float sc = g[tid] * rsqrtf(var + 1e-5f);
        ssc[tid] = sc;
        ssh[tid] = b[tid] - sc * mean;
    }
    __syncthreads();
    int gt = blockIdx.x * blockDim.x + tid;
    int node = gt >> 5, lane = gt & 31;
    if (node >= n) return;
    float2 u = ((const float2*)g_u)[node * 32 + lane];
    int c = 2 * lane;
    float y0 = lrelu(ssc[c] * u.x + ssh[c]);
    float y1 = lrelu(ssc[c + 1] * u.y + ssh[c + 1]);
    float p = y0 * fcW2[c] + y1 * fcW2[c + 1];
    #pragma unroll
    for (int o = 16; o > 0; o >>= 1) p += __shfl_xor_sync(0xffffffffu, p, o);
    if (lane == 0) out[node] = 1.0f / (1.0f + expf(-(p + fcb2[0])));
}

// ---------------- launch -------------------------------------------------------
extern "C" void kernel_launch(void* const* d_in, const int* in_sizes, int n_in,
                              void* d_out, int out_size) {
    const int*   node_deg = (const int*)d_in[0];
    const int*   edge_idx = (const int*)d_in[1];
    const float* embed    = (const float*)d_in[2];
    const float* eps      = (const float*)d_in[3];
    const float* W1       = (const float*)d_in[4];
    const float* b1       = (const float*)d_in[5];
    const float* W2       = (const float*)d_in[6];
    const float* b2       = (const float*)d_in[7];
    const float* bn_g     = (const float*)d_in[8];
    const float* bn_b     = (const float*)d_in[9];
    const float* fcW1     = (const float*)d_in[10];
    const float* fcb1     = (const float*)d_in[11];
    const float* fc_bn_g  = (const float*)d_in[12];
    const float* fc_bn_b  = (const float*)d_in[13];
    const float* fcW2     = (const float*)d_in[14];
    const float* fcb2     = (const float*)d_in[15];

    int n = in_sizes[0];
    int e = in_sizes[1] / 2;
    const int* src = edge_idx;
    const int* dst = edge_idx + e;

    int elemBlocks = (n * 32 + 255) / 256;
    int nb = (n + 1023) / 1024;
    const int PGRID = 592;

    bool vec4 = ((e & 3) == 0)
             && ((((unsigned long long)(size_t)src) & 15ull) == 0)
             && ((((unsigned long long)(size_t)dst) & 15ull) == 0);

    // embed first: fills z0 AND zeroes g_cursor + all stats slots
    k_embed<<<elemBlocks, 256>>>(node_deg, embed, n);
    if (vec4) k_hist4<<<1024, 256>>>(dst, e / 4, e);
    else      k_hist<<<1024, 256>>>(dst, e);
    k_scan1<<<nb, 1024>>>(n);
    k_scan2<<<1, 128>>>(nb);
    k_scan3<<<nb, 1024>>>(n, e);
    if (vec4) k_fill4<<<1024, 256>>>(src, dst, e / 4, e);
    else      k_fill<<<1024, 256>>>(src, dst, e);

    for (int l = 0; l < 3; l++) {
        k_layer<<<PGRID, 256>>>(W1, b1, W2, b2, eps, l, n);
        k_bnapply<<<elemBlocks, 256>>>(bn_g + l * 64, bn_b + l * 64, l + 1, n);
    }

    k_fc<<<PGRID, 256>>>(fcW1, fcb1, 0, n);
    k_fc<<<PGRID, 256>>>(fcW1, fcb1, 1, n);
    k_head<<<elemBlocks, 256>>>(fc_bn_g, fc_bn_b, fcW2, fcb2, (float*)d_out, n);
}

// round 13
// speedup vs baseline: 1.5895x; 1.0109x over previous
#include <cuda_runtime.h>
#include <cuda_bf16.h>
#include <stdint.h>
#include <math.h>

#define MAXN 100000
#define MAXE 3200000

// ---------------- scratch (static device globals) ---------------------------
__device__ int          g_cursor[MAXN];
__device__ int          g_rowptr[MAXN + 1];
__device__ int          g_col[MAXE];
__device__ int          g_bsum[256];
__device__ float        g_z[4][MAXN * 64];     // fp32 master copies z0..z3 (z3 stays RAW pre-BN)
__device__ unsigned int g_zh[3][MAXN * 32];    // bf16x2 gather copies (z3 never gathered)
__device__ float        g_u[MAXN * 64];
__device__ float        g_statsA[4][128];      // per-layer sums: [slot][0:64)=sum, [64:128)=sumsq

__device__ __forceinline__ float lrelu(float x) { return x >= 0.f ? x : 0.01f * x; }

__device__ __forceinline__ unsigned int pack_bf16x2(float2 v) {
    __nv_bfloat162 b = __float22bfloat162_rn(v);
    return *(unsigned int*)&b;
}
__device__ __forceinline__ float bf_lo(unsigned int w) { return __int_as_float((int)(w << 16)); }
__device__ __forceinline__ float bf_hi(unsigned int w) { return __int_as_float((int)(w & 0xffff0000u)); }

// ---------------- CSR build --------------------------------------------------
__global__ void k_hist4(const int* __restrict__ dst, int e4, int e) {
    int stride = gridDim.x * blockDim.x;
    int t0 = blockIdx.x * blockDim.x + threadIdx.x;
    const int4* d4 = (const int4*)dst;
    for (int i = t0; i < e4; i += stride) {
        int4 d = d4[i];
        atomicAdd(&g_cursor[d.x], 1);
        atomicAdd(&g_cursor[d.y], 1);
        atomicAdd(&g_cursor[d.z], 1);
        atomicAdd(&g_cursor[d.w], 1);
    }
    for (int i = e4 * 4 + t0; i < e; i += stride)
        atomicAdd(&g_cursor[dst[i]], 1);
}

__global__ void k_scan1(int n) {
    __shared__ int wsum[32];
    int tid = threadIdx.x, lane = tid & 31, w = tid >> 5;
    int i = blockIdx.x * 1024 + tid;
    int v = (i < n) ? g_cursor[i] : 0;
    int x = v;
    #pragma unroll
    for (int off = 1; off < 32; off <<= 1) {
        int t = __shfl_up_sync(0xffffffffu, x, off);
        if (lane >= off) x += t;
    }
    if (lane == 31) wsum[w] = x;
    __syncthreads();
    if (w == 0) {
        int s = wsum[lane];
        #pragma unroll
        for (int off = 1; off < 32; off <<= 1) {
            int t = __shfl_up_sync(0xffffffffu, s, off);
            if (lane >= off) s += t;
        }
        wsum[lane] = s;
    }
    __syncthreads();
    int incl = x + (w > 0 ? wsum[w - 1] : 0);
    if (i < n) g_rowptr[i] = incl - v;
    if (tid == 1023) g_bsum[blockIdx.x] = incl;
}

__global__ void k_scan2(int nb) {
    __shared__ int ws[4];
    int tid = threadIdx.x, lane = tid & 31, w = tid >> 5;
    int v = (tid < nb) ? g_bsum[tid] : 0;
    int x = v;
    #pragma unroll
    for (int off = 1; off < 32; off <<= 1) {
        int t = __shfl_up_sync(0xffffffffu, x, off);
        if (lane >= off) x += t;
    }
    if (lane == 31) ws[w] = x;
    __syncthreads();
    if (tid == 0) {
        int c = 0;
        #pragma unroll
        for (int k = 0; k < 4; k++) { int t = ws[k]; ws[k] = c; c += t; }
    }
    __syncthreads();
    if (tid < nb) g_bsum[tid] = x - v + ws[w];
}

__global__ void k_scan3(int n, int e) {
    int i = blockIdx.x * 1024 + threadIdx.x;
    if (i < n) {
        int v = g_rowptr[i] + g_bsum[blockIdx.x];
        g_rowptr[i] = v;
        g_cursor[i] = v;
    }
    if (i == 0) g_rowptr[n] = e;
}

__global__ void k_fill4(const int* __restrict__ src, const int* __restrict__ dst, int e4, int e) {
    int stride = gridDim.x * blockDim.x;
    int t0 = blockIdx.x * blockDim.x + threadIdx.x;
    const int4* s4 = (const int4*)src;
    const int4* d4 = (const int4*)dst;
    for (int i = t0; i < e4; i += stride) {
        int4 d = d4[i];
        int4 s = s4[i];
        int p0 = atomicAdd(&g_cursor[d.x], 1);
        int p1 = atomicAdd(&g_cursor[d.y], 1);
        int p2 = atomicAdd(&g_cursor[d.z], 1);
        int p3 = atomicAdd(&g_cursor[d.w], 1);
        g_col[p0] = s.x; g_col[p1] = s.y; g_col[p2] = s.z; g_col[p3] = s.w;
    }
    for (int i = e4 * 4 + t0; i < e; i += stride) {
        int p = atomicAdd(&g_cursor[dst[i]], 1);
        g_col[p] = src[i];
    }
}

__global__ void k_hist(const int* __restrict__ dst, int e) {
    int stride = gridDim.x * blockDim.x;
    for (int i = blockIdx.x * blockDim.x + threadIdx.x; i < e; i += stride)
        atomicAdd(&g_cursor[dst[i]], 1);
}
__global__ void k_fill(const int* __restrict__ src, const int* __restrict__ dst, int e) {
    int stride = gridDim.x * blockDim.x;
    for (int i = blockIdx.x * blockDim.x + threadIdx.x; i < e; i += stride) {
        int p = atomicAdd(&g_cursor[dst[i]], 1);
        g_col[p] = src[i];
    }
}

// ---------------- embedding lookup (also zeroes cursor + all stats slots) ----
__global__ void k_embed(const int* __restrict__ deg, const float* __restrict__ emb, int n) {
    int i = blockIdx.x * blockDim.x + threadIdx.x;
    if (i < 512) ((float*)g_statsA)[i] = 0.f;
    if (i < n) g_cursor[i] = 0;
    if (i >= n * 32) return;
    int node = i >> 5, j = i & 31;
    float2 v = ((const float2*)emb)[deg[node] * 32 + j];
    ((float2*)g_z[0])[i] = v;
    g_zh[0][i] = pack_bf16x2(v);
}

// ---------------- fused GIN layer: smem-staged gather + dual GEMVs ------------
__global__ void __launch_bounds__(256) k_layer(
    const float* __restrict__ W1, const float* __restrict__ b1,
    const float* __restrict__ W2, const float* __restrict__ b2,
    const float* __restrict__ epsArr, int l, int n)
{
    __shared__ float4 sW1q[32][32];
    __shared__ float4 sW2q[32][32];
    __shared__ float2 sb1[32];
    __shared__ float2 sb2[32];
    __shared__ float4 sm4[8][2][16];
    __shared__ float4 sh4[8][2][16];
    __shared__ int    sidx[8][2][32];
    __shared__ float  bstat[128];

    int tid = threadIdx.x;
    {
        const float2* w1v = (const float2*)(W1 + l * 4096);
        const float2* w2v = (const float2*)(W2 + l * 4096);
        for (int i = tid; i < 1024; i += 256) {
            int k2 = i >> 5, c = i & 31;
            float2 a = w1v[(2 * k2) * 32 + c];
            float2 b = w1v[(2 * k2 + 1) * 32 + c];
            sW1q[k2][c] = make_float4(a.x, a.y, b.x, b.y);
            float2 a2 = w2v[(2 * k2) * 32 + c];
            float2 b2v = w2v[(2 * k2 + 1) * 32 + c];
            sW2q[k2][c] = make_float4(a2.x, a2.y, b2v.x, b2v.y);
        }
        if (tid < 32) {
            sb1[tid] = ((const float2*)(b1 + l * 64))[tid];
            sb2[tid] = ((const float2*)(b2 + l * 64))[tid];
        }
        if (tid < 128) bstat[tid] = 0.f;
    }
    __syncthreads();

    float ep = 1.0f + epsArr[l];
    const float2*       __restrict__ x2 = (const float2*)g_z[l];
    const unsigned int* __restrict__ xh = g_zh[l];
    float2* o2 = (float2*)g_z[l + 1];
    int w = tid >> 5, lane = tid & 31;
    float ssx = 0.f, ssy = 0.f, sqx = 0.f, sqy = 0.f;
    int gw = (blockIdx.x * 256 + tid) >> 5;
    int nw = (gridDim.x * 256) >> 5;

    for (int base = gw * 2; base < n; base += nw * 2) {
        int nA = base, nB = base + 1;
        bool hasB = (nB < n);

        int bA = g_rowptr[nA], reA = g_rowptr[nA + 1];
        int bB = hasB ? g_rowptr[nB] : 0, reB = hasB ? g_rowptr[nB + 1] : 0;
        float2 xvA = x2[nA * 32 + lane];
        float2 xvB = hasB ? x2[nB * 32 + lane] : make_float2(0.f, 0.f);
        float aA0x = ep * xvA.x, aA0y = ep * xvA.y, aA1x = 0.f, aA1y = 0.f;
        float aB0x = ep * xvB.x, aB0y = ep * xvB.y, aB1x = 0.f, aB1y = 0.f;

        const int4* iA4 = (const int4*)sidx[w][0];
        const int4* iB4 = (const int4*)sidx[w][1];

        while (bA + 32 <= reA && bB + 32 <= reB) {
            sidx[w][0][lane] = g_col[bA + lane];
            sidx[w][1][lane] = g_col[bB + lane];
            __syncwarp();
            #pragma unroll
            for (int q = 0; q < 8; q++) {
                int4 ja = iA4[q];
                int4 jb = iB4[q];
                unsigned int wA0 = xh[ja.x * 32 + lane];
                unsigned int wA1 = xh[ja.y * 32 + lane];
                unsigned int wB0 = xh[jb.x * 32 + lane];
                unsigned int wB1 = xh[jb.y * 32 + lane];
                unsigned int wA2 = xh[ja.z * 32 + lane];
                unsigned int wA3 = xh[ja.w * 32 + lane];
                unsigned int wB2 = xh[jb.z * 32 + lane];
                unsigned int wB3 = xh[jb.w * 32 + lane];
                aA0x += bf_lo(wA0); aA0y += bf_hi(wA0);
                aA1x += bf_lo(wA1); aA1y += bf_hi(wA1);
                aB0x += bf_lo(wB0); aB0y += bf_hi(wB0);
                aB1x += bf_lo(wB1); aB1y += bf_hi(wB1);
                aA0x += bf_lo(wA2); aA0y += bf_hi(wA2);
                aA1x += bf_lo(wA3); aA1y += bf_hi(wA3);
                aB0x += bf_lo(wB2); aB0y += bf_hi(wB2);
                aB1x += bf_lo(wB3); aB1y += bf_hi(wB3);
            }
            __syncwarp();
            bA += 32; bB += 32;
        }
        while (bA + 32 <= reA) {
            sidx[w][0][lane] = g_col[bA + lane];
            __syncwarp();
            #pragma unroll
            for (int q = 0; q < 8; q++) {
                int4 ja = iA4[q];
                unsigned int w0 = xh[ja.x * 32 + lane];
                unsigned int w1 = xh[ja.y * 32 + lane];
                unsigned int w2 = xh[ja.z * 32 + lane];
                unsigned int w3 = xh[ja.w * 32 + lane];
                aA0x += bf_lo(w0); aA0y += bf_hi(w0);
                aA1x += bf_lo(w1); aA1y += bf_hi(w1);
                aA0x += bf_lo(w2); aA0y += bf_hi(w2);
                aA1x += bf_lo(w3); aA1y += bf_hi(w3);
            }
            __syncwarp();
            bA += 32;
        }
        while (bB + 32 <= reB) {
            sidx[w][1][lane] = g_col[bB + lane];
            __syncwarp();
            #pragma unroll
            for (int q = 0; q < 8; q++) {
                int4 jb = iB4[q];
                unsigned int w0 = xh[jb.x * 32 + lane];
                unsigned int w1 = xh[jb.y * 32 + lane];
                unsigned int w2 = xh[jb.z * 32 + lane];
                unsigned int w3 = xh[jb.w * 32 + lane];
                aB0x += bf_lo(w0); aB0y += bf_hi(w0);
                aB1x += bf_lo(w1); aB1y += bf_hi(w1);
                aB0x += bf_lo(w2); aB0y += bf_hi(w2);
                aB1x += bf_lo(w3); aB1y += bf_hi(w3);
            }
            __syncwarp();
            bB += 32;
        }
        {
            int remA = reA - bA, remB = reB - bB;
            if (lane < remA) sidx[w][0][lane] = g_col[bA + lane];
            if (lane < remB) sidx[w][1][lane] = g_col[bB + lane];
            __syncwarp();
            int rem = remA > remB ? remA : remB;
            for (int t = 0; t < rem; t++) {
                if (t < remA) {
                    unsigned int wv = xh[sidx[w][0][t] * 32 + lane];
                    aA0x += bf_lo(wv); aA0y += bf_hi(wv);
                }
                if (t < remB) {
                    unsigned int wv = xh[sidx[w][1][t] * 32 + lane];
                    aB0x += bf_lo(wv); aB0y += bf_hi(wv);
                }
            }
            __syncwarp();
        }
        ((float2*)sm4[w][0])[lane] = make_float2(aA0x + aA1x, aA0y + aA1y);
        ((float2*)sm4[w][1])[lane] = make_float2(aB0x + aB1x, aB0y + aB1y);
        __syncwarp();

        // ------- dual GEMV1 (frozen) -------
        float2 hA = sb1[lane], hB = sb1[lane];
        const float4* mAv = (const float4*)sm4[w][0];
        const float4* mBv = (const float4*)sm4[w][1];
        #pragma unroll
        for (int kk = 0; kk < 16; kk++) {
            float4 m4A = mAv[kk];
            float4 m4B = mBv[kk];
            float4 w0 = sW1q[2 * kk][lane];
            float4 w1 = sW1q[2 * kk + 1][lane];
            hA.x = fmaf(m4A.x, w0.x, hA.x); hA.y = fmaf(m4A.x, w0.y, hA.y);
            hA.x = fmaf(m4A.y, w0.z, hA.x); hA.y = fmaf(m4A.y, w0.w, hA.y);
            hA.x = fmaf(m4A.z, w1.x, hA.x); hA.y = fmaf(m4A.z, w1.y, hA.y);
            hA.x = fmaf(m4A.w, w1.z, hA.x); hA.y = fmaf(m4A.w, w1.w, hA.y);
            hB.x = fmaf(m4B.x, w0.x, hB.x); hB.y = fmaf(m4B.x, w0.y, hB.y);
            hB.x = fmaf(m4B.y, w0.z, hB.x); hB.y = fmaf(m4B.y, w0.w, hB.y);
            hB.x = fmaf(m4B.z, w1.x, hB.x); hB.y = fmaf(m4B.z, w1.y, hB.y);
            hB.x = fmaf(m4B.w, w1.z, hB.x); hB.y = fmaf(m4B.w, w1.w, hB.y);
        }
        hA.x = lrelu(hA.x); hA.y = lrelu(hA.y);
        hB.x = lrelu(hB.x); hB.y = lrelu(hB.y);
        ((float2*)sh4[w][0])[lane] = hA;
        ((float2*)sh4[w][1])[lane] = hB;
        __syncwarp();

        // ------- dual GEMV2 (frozen) -------
        float2 oA = sb2[lane], oB = sb2[lane];
        const float4* hAv = (const float4*)sh4[w][0];
        const float4* hBv = (const float4*)sh4[w][1];
        #pragma unroll
        for (int kk = 0; kk < 16; kk++) {
            float4 m4A = hAv[kk];
            float4 m4B = hBv[kk];
            float4 w0 = sW2q[2 * kk][lane];
            float4 w1 = sW2q[2 * kk + 1][lane];
            oA.x = fmaf(m4A.x, w0.x, oA.x); oA.y = fmaf(m4A.x, w0.y, oA.y);
            oA.x = fmaf(m4A.y, w0.z, oA.x); oA.y = fmaf(m4A.y, w0.w, oA.y);
            oA.x = fmaf(m4A.z, w1.x, oA.x); oA.y = fmaf(m4A.z, w1.y, oA.y);
            oA.x = fmaf(m4A.w, w1.z, oA.x); oA.y = fmaf(m4A.w, w1.w, oA.y);
            oB.x = fmaf(m4B.x, w0.x, oB.x); oB.y = fmaf(m4B.x, w0.y, oB.y);
            oB.x = fmaf(m4B.y, w0.z, oB.x); oB.y = fmaf(m4B.y, w0.w, oB.y);
            oB.x = fmaf(m4B.z, w1.x, oB.x); oB.y = fmaf(m4B.z, w1.y, oB.y);
            oB.x = fmaf(m4B.w, w1.z, oB.x); oB.y = fmaf(m4B.w, w1.w, oB.y);
        }
        o2[nA * 32 + lane] = oA;
        ssx += oA.x; ssy += oA.y; sqx += oA.x * oA.x; sqy += oA.y * oA.y;
        if (hasB) {
            o2[nB * 32 + lane] = oB;
            ssx += oB.x; ssy += oB.y; sqx += oB.x * oB.x; sqy += oB.y * oB.y;
        }
        __syncwarp();
    }

    atomicAdd(&bstat[2 * lane], ssx);
    atomicAdd(&bstat[2 * lane + 1], ssy);
    atomicAdd(&bstat[64 + 2 * lane], sqx);
    atomicAdd(&bstat[64 + 2 * lane + 1], sqy);
    __syncthreads();
    if (tid < 128) atomicAdd(&g_statsA[l][tid], bstat[tid]);
}

// ---------------- BN + leaky for z1/z2 (params computed per-block in smem) ----
__global__ void k_bnapply(const float* __restrict__ g, const float* __restrict__ b,
                          int lz, int n) {
    __shared__ float ssc[64];
    __shared__ float ssh[64];
    int tid = threadIdx.x;
    int slot = lz - 1;
    if (tid < 64) {
        float inv = 1.0f / (float)n;
        float mean = g_statsA[slot][tid] * inv;
        float var = g_statsA[slot][64 + tid] * inv - mean * mean;
        float sc = g[tid] * rsqrtf(var + 1e-5f);
        ssc[tid] = sc;
        ssh[tid] = b[tid] - sc * mean;
    }
    __syncthreads();
    int i = blockIdx.x * blockDim.x + tid;
    if (i >= n * 32) return;
    int c = (i & 31) * 2;
    float2* z2 = (float2*)g_z[lz];
    float2 v = z2[i];
    v.x = lrelu(ssc[c] * v.x + ssh[c]);
    v.y = lrelu(ssc[c + 1] * v.y + ssh[c + 1]);
    z2[i] = v;
    g_zh[lz][i] = pack_bf16x2(v);
}

// ---------------- FC layer 1: chunk1 applies z3's BN on the fly ----------------
__global__ void __launch_bounds__(256) k_fc(
    const float* __restrict__ fcW1, const float* __restrict__ fcb1,
    const float* __restrict__ bng, const float* __restrict__ bnb,
    int chunk, int n)
{
    __shared__ float4 sWq[64][32];
    __shared__ float4 sx4[8][2][32];
    __shared__ float2 sb[32];
    __shared__ float  bstat[128];
    __shared__ float  ssc[64];
    __shared__ float  ssh[64];
    int tid = threadIdx.x;
    {
        const float2* wv = (const float2*)(fcW1 + chunk * 128 * 64);
        for (int i = tid; i < 2048; i += 256) {
            int k2 = i >> 5, c = i & 31;
            float2 a = wv[(2 * k2) * 32 + c];
            float2 b = wv[(2 * k2 + 1) * 32 + c];
            sWq[k2][c] = make_float4(a.x, a.y, b.x, b.y);
        }
        if (tid < 32) sb[tid] = (chunk == 0) ? ((const float2*)fcb1)[tid] : make_float2(0.f, 0.f);
        if (tid < 128) bstat[tid] = 0.f;
        if (chunk == 1 && tid < 64) {
            // BN params for z3 (stats slot 2), applied on the fly to zb loads
            float inv = 1.0f / (float)n;
            float mean = g_statsA[2][tid] * inv;
            float var = g_statsA[2][64 + tid] * inv - mean * mean;
            float sc = bng[tid] * rsqrtf(var + 1e-5f);
            ssc[tid] = sc;
            ssh[tid] = bnb[tid] - sc * mean;
        }
    }
    __syncthreads();

    const float2* za = (const float2*)g_z[2 * chunk];
    const float2* zb = (const float2*)g_z[2 * chunk + 1];
    float2* u2 = (float2*)g_u;
    int w = tid >> 5, lane = tid & 31;
    float ssx = 0.f, ssy = 0.f, sqx = 0.f, sqy = 0.f;
    int gw = (blockIdx.x * 256 + tid) >> 5;
    int nw = (gridDim.x * 256) >> 5;
    float scx = 0.f, scy = 0.f, shx = 0.f, shy = 0.f;
    if (chunk == 1) {
        scx = ssc[2 * lane]; scy = ssc[2 * lane + 1];
        shx = ssh[2 * lane]; shy = ssh[2 * lane + 1];
    }

    for (int base = gw * 2; base < n; base += nw * 2) {
        int nA = base, nB = base + 1;
        bool hasB = (nB < n);
        float2 vbA = zb[nA * 32 + lane];
        if (chunk == 1) {
            vbA.x = lrelu(scx * vbA.x + shx);
            vbA.y = lrelu(scy * vbA.y + shy);
        }
        ((float2*)sx4[w][0])[lane]      = za[nA * 32 + lane];
        ((float2*)sx4[w][0])[32 + lane] = vbA;
        if (hasB) {
            float2 vbB = zb[nB * 32 + lane];
            if (chunk == 1) {
                vbB.x = lrelu(scx * vbB.x + shx);
                vbB.y = lrelu(scy * vbB.y + shy);
            }
            ((float2*)sx4[w][1])[lane]      = za[nB * 32 + lane];
            ((float2*)sx4[w][1])[32 + lane] = vbB;
        }
        __syncwarp();

        float2 uA = (chunk == 0) ? sb[lane] : u2[nA * 32 + lane];
        float2 uB = (chunk == 0) ? sb[lane] : (hasB ? u2[nB * 32 + lane] : make_float2(0.f, 0.f));
        const float4* xAv = (const float4*)sx4[w][0];
        const float4* xBv = (const float4*)sx4[w][1];
        #pragma unroll
        for (int kk = 0; kk < 32; kk++) {
            float4 m4A = xAv[kk];
            float4 m4B = xBv[kk];
            float4 w0 = sWq[2 * kk][lane];
            float4 w1 = sWq[2 * kk + 1][lane];
            uA.x = fmaf(m4A.x, w0.x, uA.x); uA.y = fmaf(m4A.x, w0.y, uA.y);
            uA.x = fmaf(m4A.y, w0.z, uA.x); uA.y = fmaf(m4A.y, w0.w, uA.y);
            uA.x = fmaf(m4A.z, w1.x, uA.x); uA.y = fmaf(m4A.z, w1.y, uA.y);
            uA.x = fmaf(m4A.w, w1.z, uA.x); uA.y = fmaf(m4A.w, w1.w, uA.y);
            uB.x = fmaf(m4B.x, w0.x, uB.x); uB.y = fmaf(m4B.x, w0.y, uB.y);
            uB.x = fmaf(m4B.y, w0.z, uB.x); uB.y = fmaf(m4B.y, w0.w, uB.y);
            uB.x = fmaf(m4B.z, w1.x, uB.x); uB.y = fmaf(m4B.z, w1.y, uB.y);
            uB.x = fmaf(m4B.w, w1.z, uB.x); uB.y = fmaf(m4B.w, w1.w, uB.y);
        }
        u2[nA * 32 + lane] = uA;
        if (chunk == 1) { ssx += uA.x; ssy += uA.y; sqx += uA.x * uA.x; sqy += uA.y * uA.y; }
        if (hasB) {
            u2[nB * 32 + lane] = uB;
            if (chunk == 1) { ssx += uB.x; ssy += uB.y; sqx += uB.x * uB.x; sqy += uB.y * uB.y; }
        }
        __syncwarp();
    }

    if (chunk == 1) {
        atomicAdd(&bstat[2 * lane], ssx);
        atomicAdd(&bstat[2 * lane + 1], ssy);
        atomicAdd(&bstat[64 + 2 * lane], sqx);
        atomicAdd(&bstat[64 + 2 * lane + 1], sqy);
        __syncthreads();
        if (tid < 128) atomicAdd(&g_statsA[3][tid], bstat[tid]);
    }
}

// ---------------- head: params in smem + BN + leaky + dot + sigmoid -----------
__global__ void k_head(const float* __restrict__ g, const float* __restrict__ b,
                       const float* __restrict__ fcW2, const float* __restrict__ fcb2,
                       float* __restrict__ out, int n) {
    __shared__ float ssc[64];
    __shared__ float ssh[64];
    int tid = threadIdx.x;
    if (tid < 64) {
        float inv = 1.0f / (float)n;
        float mean = g_statsA[3][tid] * inv;
        float var = g_statsA[3][64 + tid] * inv - mean * mean;
        float sc = g[tid] * rsqrtf(var + 1e-5f);
        ssc[tid] = sc;
        ssh[tid] = b[tid] - sc * mean;
    }
    __syncthreads();
    int gt = blockIdx.x * blockDim.x + tid;
    int node = gt >> 5, lane = gt & 31;
    if (node >= n) return;
    float2 u = ((const float2*)g_u)[node * 32 + lane];
    int c = 2 * lane;
    float y0 = lrelu(ssc[c] * u.x + ssh[c]);
    float y1 = lrelu(ssc[c + 1] * u.y + ssh[c + 1]);
    float p = y0 * fcW2[c] + y1 * fcW2[c + 1];
    #pragma unroll
    for (int o = 16; o > 0; o >>= 1) p += __shfl_xor_sync(0xffffffffu, p, o);
    if (lane == 0) out[node] = 1.0f / (1.0f + expf(-(p + fcb2[0])));
}

// ---------------- launch -------------------------------------------------------
extern "C" void kernel_launch(void* const* d_in, const int* in_sizes, int n_in,
                              void* d_out, int out_size) {
    const int*   node_deg = (const int*)d_in[0];
    const int*   edge_idx = (const int*)d_in[1];
    const float* embed    = (const float*)d_in[2];
    const float* eps      = (const float*)d_in[3];
    const float* W1       = (const float*)d_in[4];
    const float* b1       = (const float*)d_in[5];
    const float* W2       = (const float*)d_in[6];
    const float* b2       = (const float*)d_in[7];
    const float* bn_g     = (const float*)d_in[8];
    const float* bn_b     = (const float*)d_in[9];
    const float* fcW1     = (const float*)d_in[10];
    const float* fcb1     = (const float*)d_in[11];
    const float* fc_bn_g  = (const float*)d_in[12];
    const float* fc_bn_b  = (const float*)d_in[13];
    const float* fcW2     = (const float*)d_in[14];
    const float* fcb2     = (const float*)d_in[15];

    int n = in_sizes[0];
    int e = in_sizes[1] / 2;
    const int* src = edge_idx;
    const int* dst = edge_idx + e;

    int elemBlocks = (n * 32 + 255) / 256;
    int nb = (n + 1023) / 1024;
    const int PGRID = 592;

    bool vec4 = ((e & 3) == 0)
             && ((((unsigned long long)(size_t)src) & 15ull) == 0)
             && ((((unsigned long long)(size_t)dst) & 15ull) == 0);

    k_embed<<<elemBlocks, 256>>>(node_deg, embed, n);
    if (vec4) k_hist4<<<1024, 256>>>(dst, e / 4, e);
    else      k_hist<<<1024, 256>>>(dst, e);
    k_scan1<<<nb, 1024>>>(n);
    k_scan2<<<1, 128>>>(nb);
    k_scan3<<<nb, 1024>>>(n, e);
    if (vec4) k_fill4<<<1024, 256>>>(src, dst, e / 4, e);
    else      k_fill<<<1024, 256>>>(src, dst, e);

    // layers 0,1: BN applied by k_bnapply (z1,z2 need fp32+bf16 normalized copies)
    for (int l = 0; l < 2; l++) {
        k_layer<<<PGRID, 256>>>(W1, b1, W2, b2, eps, l, n);
        k_bnapply<<<elemBlocks, 256>>>(bn_g + l * 64, bn_b + l * 64, l + 1, n);
    }
    // layer 2: z3 stays raw; its BN+lrelu is fused into k_fc chunk 1
    k_layer<<<PGRID, 256>>>(W1, b1, W2, b2, eps, 2, n);

    k_fc<<<PGRID, 256>>>(fcW1, fcb1, bn_g + 128, bn_b + 128, 0, n);
    k_fc<<<PGRID, 256>>>(fcW1, fcb1, bn_g + 128, bn_b + 128, 1, n);
    k_head<<<elemBlocks, 256>>>(fc_bn_g, fc_bn_b, fcW2, fcb2, (float*)d_out, n);
}

// round 15
// speedup vs baseline: 1.6396x; 1.0315x over previous
#include <cuda_runtime.h>
#include <cuda_bf16.h>
#include <stdint.h>
#include <math.h>

#define MAXN 100000
#define MAXE 3200000

// ---------------- scratch (static device globals) ---------------------------
__device__ int          g_cursor[MAXN];
__device__ int          g_rowptr[MAXN + 1];
__device__ int          g_col[MAXE];
__device__ int          g_bsum[256];
__device__ int          g_ticket[8];           // dynamic work counters (per layer)
__device__ float        g_z[4][MAXN * 64];     // fp32 master copies z0..z3 (z3 stays RAW pre-BN)
__device__ unsigned int g_zh[3][MAXN * 32];    // bf16x2 gather copies (z3 never gathered)
__device__ float        g_u[MAXN * 64];
__device__ float        g_statsA[4][128];      // per-layer sums: [slot][0:64)=sum, [64:128)=sumsq

__device__ __forceinline__ float lrelu(float x) { return x >= 0.f ? x : 0.01f * x; }

__device__ __forceinline__ unsigned int pack_bf16x2(float2 v) {
    __nv_bfloat162 b = __float22bfloat162_rn(v);
    return *(unsigned int*)&b;
}
__device__ __forceinline__ float bf_lo(unsigned int w) { return __int_as_float((int)(w << 16)); }
__device__ __forceinline__ float bf_hi(unsigned int w) { return __int_as_float((int)(w & 0xffff0000u)); }

// ---------------- init: zero cursor + stats + tickets -------------------------
__global__ void k_zero(int n) {
    int i = blockIdx.x * blockDim.x + threadIdx.x;
    if (i < n) g_cursor[i] = 0;
    if (i < 512) ((float*)g_statsA)[i] = 0.f;
    if (i < 8) g_ticket[i] = 0;
}

// ---------------- fused hist + embed (independent work overlaps) --------------
__global__ void k_hist4e(const int* __restrict__ dst, int e4, int e,
                         const int* __restrict__ deg, const float* __restrict__ emb, int n) {
    int stride = gridDim.x * blockDim.x;
    int t0 = blockIdx.x * blockDim.x + threadIdx.x;
    const int4* d4 = (const int4*)dst;
    for (int i = t0; i < e4; i += stride) {
        int4 d = d4[i];
        atomicAdd(&g_cursor[d.x], 1);
        atomicAdd(&g_cursor[d.y], 1);
        atomicAdd(&g_cursor[d.z], 1);
        atomicAdd(&g_cursor[d.w], 1);
    }
    for (int i = e4 * 4 + t0; i < e; i += stride)
        atomicAdd(&g_cursor[dst[i]], 1);
    // embedding lookup (fills latency bubbles of the atomics above)
    int total = n * 32;
    for (int i = t0; i < total; i += stride) {
        int node = i >> 5, j = i & 31;
        float2 v = ((const float2*)emb)[deg[node] * 32 + j];
        ((float2*)g_z[0])[i] = v;
        g_zh[0][i] = pack_bf16x2(v);
    }
}

// scalar fallbacks
__global__ void k_hist(const int* __restrict__ dst, int e) {
    int stride = gridDim.x * blockDim.x;
    for (int i = blockIdx.x * blockDim.x + threadIdx.x; i < e; i += stride)
        atomicAdd(&g_cursor[dst[i]], 1);
}
__global__ void k_embed(const int* __restrict__ deg, const float* __restrict__ emb, int n) {
    int i = blockIdx.x * blockDim.x + threadIdx.x;
    if (i >= n * 32) return;
    int node = i >> 5, j = i & 31;
    float2 v = ((const float2*)emb)[deg[node] * 32 + j];
    ((float2*)g_z[0])[i] = v;
    g_zh[0][i] = pack_bf16x2(v);
}
__global__ void k_fill(const int* __restrict__ src, const int* __restrict__ dst, int e) {
    int stride = gridDim.x * blockDim.x;
    for (int i = blockIdx.x * blockDim.x + threadIdx.x; i < e; i += stride) {
        int p = atomicAdd(&g_cursor[dst[i]], 1);
        g_col[p] = src[i];
    }
}

__global__ void k_scan1(int n) {
    __shared__ int wsum[32];
    int tid = threadIdx.x, lane = tid & 31, w = tid >> 5;
    int i = blockIdx.x * 1024 + tid;
    int v = (i < n) ? g_cursor[i] : 0;
    int x = v;
    #pragma unroll
    for (int off = 1; off < 32; off <<= 1) {
        int t = __shfl_up_sync(0xffffffffu, x, off);
        if (lane >= off) x += t;
    }
    if (lane == 31) wsum[w] = x;
    __syncthreads();
    if (w == 0) {
        int s = wsum[lane];
        #pragma unroll
        for (int off = 1; off < 32; off <<= 1) {
            int t = __shfl_up_sync(0xffffffffu, s, off);
            if (lane >= off) s += t;
        }
        wsum[lane] = s;
    }
    __syncthreads();
    int incl = x + (w > 0 ? wsum[w - 1] : 0);
    if (i < n) g_rowptr[i] = incl - v;
    if (tid == 1023) g_bsum[blockIdx.x] = incl;
}

__global__ void k_scan2(int nb) {
    __shared__ int ws[4];
    int tid = threadIdx.x, lane = tid & 31, w = tid >> 5;
    int v = (tid < nb) ? g_bsum[tid] : 0;
    int x = v;
    #pragma unroll
    for (int off = 1; off < 32; off <<= 1) {
        int t = __shfl_up_sync(0xffffffffu, x, off);
        if (lane >= off) x += t;
    }
    if (lane == 31) ws[w] = x;
    __syncthreads();
    if (tid == 0) {
        int c = 0;
        #pragma unroll
        for (int k = 0; k < 4; k++) { int t = ws[k]; ws[k] = c; c += t; }
    }
    __syncthreads();
    if (tid < nb) g_bsum[tid] = x - v + ws[w];
}

__global__ void k_scan3(int n, int e) {
    int i = blockIdx.x * 1024 + threadIdx.x;
    if (i < n) {
        int v = g_rowptr[i] + g_bsum[blockIdx.x];
        g_rowptr[i] = v;
        g_cursor[i] = v;
    }
    if (i == 0) g_rowptr[n] = e;
}

__global__ void k_fill4(const int* __restrict__ src, const int* __restrict__ dst, int e4, int e) {
    int stride = gridDim.x * blockDim.x;
    int t0 = blockIdx.x * blockDim.x + threadIdx.x;
    const int4* s4 = (const int4*)src;
    const int4* d4 = (const int4*)dst;
    for (int i = t0; i < e4; i += stride) {
        int4 d = d4[i];
        int4 s = s4[i];
        int p0 = atomicAdd(&g_cursor[d.x], 1);
        int p1 = atomicAdd(&g_cursor[d.y], 1);
        int p2 = atomicAdd(&g_cursor[d.z], 1);
        int p3 = atomicAdd(&g_cursor[d.w], 1);
        g_col[p0] = s.x; g_col[p1] = s.y; g_col[p2] = s.z; g_col[p3] = s.w;
    }
    for (int i = e4 * 4 + t0; i < e; i += stride) {
        int p = atomicAdd(&g_cursor[dst[i]], 1);
        g_col[p] = src[i];
    }
}

// ---------------- fused GIN layer: dynamic tickets + staged gather + GEMVs -----
__global__ void __launch_bounds__(256) k_layer(
    const float* __restrict__ W1, const float* __restrict__ b1,
    const float* __restrict__ W2, const float* __restrict__ b2,
    const float* __restrict__ epsArr, int l, int n)
{
    __shared__ float4 sW1q[32][32];
    __shared__ float4 sW2q[32][32];
    __shared__ float2 sb1[32];
    __shared__ float2 sb2[32];
    __shared__ float4 sm4[8][2][16];
    __shared__ float4 sh4[8][2][16];
    __shared__ int    sidx[8][2][32];
    __shared__ float  bstat[128];

    int tid = threadIdx.x;
    {
        const float2* w1v = (const float2*)(W1 + l * 4096);
        const float2* w2v = (const float2*)(W2 + l * 4096);
        for (int i = tid; i < 1024; i += 256) {
            int k2 = i >> 5, c = i & 31;
            float2 a = w1v[(2 * k2) * 32 + c];
            float2 b = w1v[(2 * k2 + 1) * 32 + c];
            sW1q[k2][c] = make_float4(a.x, a.y, b.x, b.y);
            float2 a2 = w2v[(2 * k2) * 32 + c];
            float2 b2v = w2v[(2 * k2 + 1) * 32 + c];
            sW2q[k2][c] = make_float4(a2.x, a2.y, b2v.x, b2v.y);
        }
        if (tid < 32) {
            sb1[tid] = ((const float2*)(b1 + l * 64))[tid];
            sb2[tid] = ((const float2*)(b2 + l * 64))[tid];
        }
        if (tid < 128) bstat[tid] = 0.f;
    }
    __syncthreads();

    float ep = 1.0f + epsArr[l];
    const float2*       __restrict__ x2 = (const float2*)g_z[l];
    const unsigned int* __restrict__ xh = g_zh[l];
    float2* o2 = (float2*)g_z[l + 1];
    int w = tid >> 5, lane = tid & 31;
    float ssx = 0.f, ssy = 0.f, sqx = 0.f, sqy = 0.f;
    int pairs = (n + 1) / 2;

    while (true) {
        int tk;
        if (lane == 0) tk = atomicAdd(&g_ticket[l], 1);
        tk = __shfl_sync(0xffffffffu, tk, 0);
        if (tk >= pairs) break;
        int base = tk * 2;
        int nA = base, nB = base + 1;
        bool hasB = (nB < n);

        int bA = g_rowptr[nA], reA = g_rowptr[nA + 1];
        int bB = hasB ? g_rowptr[nB] : 0, reB = hasB ? g_rowptr[nB + 1] : 0;
        float2 xvA = x2[nA * 32 + lane];
        float2 xvB = hasB ? x2[nB * 32 + lane] : make_float2(0.f, 0.f);
        float aA0x = ep * xvA.x, aA0y = ep * xvA.y, aA1x = 0.f, aA1y = 0.f;
        float aB0x = ep * xvB.x, aB0y = ep * xvB.y, aB1x = 0.f, aB1y = 0.f;

        const int4* iA4 = (const int4*)sidx[w][0];
        const int4* iB4 = (const int4*)sidx[w][1];

        while (bA + 32 <= reA && bB + 32 <= reB) {
            sidx[w][0][lane] = g_col[bA + lane];
            sidx[w][1][lane] = g_col[bB + lane];
            __syncwarp();
            #pragma unroll
            for (int q = 0; q < 8; q++) {
                int4 ja = iA4[q];
                int4 jb = iB4[q];
                unsigned int wA0 = xh[ja.x * 32 + lane];
                unsigned int wA1 = xh[ja.y * 32 + lane];
                unsigned int wB0 = xh[jb.x * 32 + lane];
                unsigned int wB1 = xh[jb.y * 32 + lane];
                unsigned int wA2 = xh[ja.z * 32 + lane];
                unsigned int wA3 = xh[ja.w * 32 + lane];
                unsigned int wB2 = xh[jb.z * 32 + lane];
                unsigned int wB3 = xh[jb.w * 32 + lane];
                aA0x += bf_lo(wA0); aA0y += bf_hi(wA0);
                aA1x += bf_lo(wA1); aA1y += bf_hi(wA1);
                aB0x += bf_lo(wB0); aB0y += bf_hi(wB0);
                aB1x += bf_lo(wB1); aB1y += bf_hi(wB1);
                aA0x += bf_lo(wA2); aA0y += bf_hi(wA2);
                aA1x += bf_lo(wA3); aA1y += bf_hi(wA3);
                aB0x += bf_lo(wB2); aB0y += bf_hi(wB2);
                aB1x += bf_lo(wB3); aB1y += bf_hi(wB3);
            }
            __syncwarp();
            bA += 32; bB += 32;
        }
        while (bA + 32 <= reA) {
            sidx[w][0][lane] = g_col[bA + lane];
            __syncwarp();
            #pragma unroll
            for (int q = 0; q < 8; q++) {
                int4 ja = iA4[q];
                unsigned int w0 = xh[ja.x * 32 + lane];
                unsigned int w1 = xh[ja.y * 32 + lane];
                unsigned int w2 = xh[ja.z * 32 + lane];
                unsigned int w3 = xh[ja.w * 32 + lane];
                aA0x += bf_lo(w0); aA0y += bf_hi(w0);
                aA1x += bf_lo(w1); aA1y += bf_hi(w1);
                aA0x += bf_lo(w2); aA0y += bf_hi(w2);
                aA1x += bf_lo(w3); aA1y += bf_hi(w3);
            }
            __syncwarp();
            bA += 32;
        }
        while (bB + 32 <= reB) {
            sidx[w][1][lane] = g_col[bB + lane];
            __syncwarp();
            #pragma unroll
            for (int q = 0; q < 8; q++) {
                int4 jb = iB4[q];
                unsigned int w0 = xh[jb.x * 32 + lane];
                unsigned int w1 = xh[jb.y * 32 + lane];
                unsigned int w2 = xh[jb.z * 32 + lane];
                unsigned int w3 = xh[jb.w * 32 + lane];
                aB0x += bf_lo(w0); aB0y += bf_hi(w0);
                aB1x += bf_lo(w1); aB1y += bf_hi(w1);
                aB0x += bf_lo(w2); aB0y += bf_hi(w2);
                aB1x += bf_lo(w3); aB1y += bf_hi(w3);
            }
            __syncwarp();
            bB += 32;
        }
        {
            int remA = reA - bA, remB = reB - bB;
            if (lane < remA) sidx[w][0][lane] = g_col[bA + lane];
            if (lane < remB) sidx[w][1][lane] = g_col[bB + lane];
            __syncwarp();
            int rem = remA > remB ? remA : remB;
            for (int t = 0; t < rem; t++) {
                if (t < remA) {
                    unsigned int wv = xh[sidx[w][0][t] * 32 + lane];
                    aA0x += bf_lo(wv); aA0y += bf_hi(wv);
                }
                if (t < remB) {
                    unsigned int wv = xh[sidx[w][1][t] * 32 + lane];
                    aB0x += bf_lo(wv); aB0y += bf_hi(wv);
                }
            }
            __syncwarp();
        }
        ((float2*)sm4[w][0])[lane] = make_float2(aA0x + aA1x, aA0y + aA1y);
        ((float2*)sm4[w][1])[lane] = make_float2(aB0x + aB1x, aB0y + aB1y);
        __syncwarp();

        // ------- dual GEMV1 (frozen) -------
        float2 hA = sb1[lane], hB = sb1[lane];
        const float4* mAv = (const float4*)sm4[w][0];
        const float4* mBv = (const float4*)sm4[w][1];
        #pragma unroll
        for (int kk = 0; kk < 16; kk++) {
            float4 m4A = mAv[kk];
            float4 m4B = mBv[kk];
            float4 w0 = sW1q[2 * kk][lane];
            float4 w1 = sW1q[2 * kk + 1][lane];
            hA.x = fmaf(m4A.x, w0.x, hA.x); hA.y = fmaf(m4A.x, w0.y, hA.y);
            hA.x = fmaf(m4A.y, w0.z, hA.x); hA.y = fmaf(m4A.y, w0.w, hA.y);
            hA.x = fmaf(m4A.z, w1.x, hA.x); hA.y = fmaf(m4A.z, w1.y, hA.y);
            hA.x = fmaf(m4A.w, w1.z, hA.x); hA.y = fmaf(m4A.w, w1.w, hA.y);
            hB.x = fmaf(m4B.x, w0.x, hB.x); hB.y = fmaf(m4B.x, w0.y, hB.y);
            hB.x = fmaf(m4B.y, w0.z, hB.x); hB.y = fmaf(m4B.y, w0.w, hB.y);
            hB.x = fmaf(m4B.z, w1.x, hB.x); hB.y = fmaf(m4B.z, w1.y, hB.y);
            hB.x = fmaf(m4B.w, w1.z, hB.x); hB.y = fmaf(m4B.w, w1.w, hB.y);
        }
        hA.x = lrelu(hA.x); hA.y = lrelu(hA.y);
        hB.x = lrelu(hB.x); hB.y = lrelu(hB.y);
        ((float2*)sh4[w][0])[lane] = hA;
        ((float2*)sh4[w][1])[lane] = hB;
        __syncwarp();

        // ------- dual GEMV2 (frozen) -------
        float2 oA = sb2[lane], oB = sb2[lane];
        const float4* hAv = (const float4*)sh4[w][0];
        const float4* hBv = (const float4*)sh4[w][1];
        #pragma unroll
        for (int kk = 0; kk < 16; kk++) {
            float4 m4A = hAv[kk];
            float4 m4B = hBv[kk];
            float4 w0 = sW2q[2 * kk][lane];
            float4 w1 = sW2q[2 * kk + 1][lane];
            oA.x = fmaf(m4A.x, w0.x, oA.x); oA.y = fmaf(m4A.x, w0.y, oA.y);
            oA.x = fmaf(m4A.y, w0.z, oA.x); oA.y = fmaf(m4A.y, w0.w, oA.y);
            oA.x = fmaf(m4A.z, w1.x, oA.x); oA.y = fmaf(m4A.z, w1.y, oA.y);
            oA.x = fmaf(m4A.w, w1.z, oA.x); oA.y = fmaf(m4A.w, w1.w, oA.y);
            oB.x = fmaf(m4B.x, w0.x, oB.x); oB.y = fmaf(m4B.x, w0.y, oB.y);
            oB.x = fmaf(m4B.y, w0.z, oB.x); oB.y = fmaf(m4B.y, w0.w, oB.y);
            oB.x = fmaf(m4B.z, w1.x, oB.x); oB.y = fmaf(m4B.z, w1.y, oB.y);
            oB.x = fmaf(m4B.w, w1.z, oB.x); oB.y = fmaf(m4B.w, w1.w, oB.y);
        }
        o2[nA * 32 + lane] = oA;
        ssx += oA.x; ssy += oA.y; sqx += oA.x * oA.x; sqy += oA.y * oA.y;
        if (hasB) {
            o2[nB * 32 + lane] = oB;
            ssx += oB.x; ssy += oB.y; sqx += oB.x * oB.x; sqy += oB.y * oB.y;
        }
        __syncwarp();
    }

    atomicAdd(&bstat[2 * lane], ssx);
    atomicAdd(&bstat[2 * lane + 1], ssy);
    atomicAdd(&bstat[64 + 2 * lane], sqx);
    atomicAdd(&bstat[64 + 2 * lane + 1], sqy);
    __syncthreads();
    if (tid < 128) atomicAdd(&g_statsA[l][tid], bstat[tid]);
}

// ---------------- BN + leaky for z1/z2 (params computed per-block in smem) ----
__global__ void k_bnapply(const float* __restrict__ g, const float* __restrict__ b,
                          int lz, int n) {
    __shared__ float ssc[64];
    __shared__ float ssh[64];
    int tid = threadIdx.x;
    int slot = lz - 1;
    if (tid < 64) {
        float inv = 1.0f / (float)n;
        float mean = g_statsA[slot][tid] * inv;
        float var = g_statsA[slot][64 + tid] * inv - mean * mean;
        float sc = g[tid] * rsqrtf(var + 1e-5f);
        ssc[tid] = sc;
        ssh[tid] = b[tid] - sc * mean;
    }
    __syncthreads();
    int i = blockIdx.x * blockDim.x + tid;
    if (i >= n * 32) return;
    int c = (i & 31) * 2;
    float2* z2 = (float2*)g_z[lz];
    float2 v = z2[i];
    v.x = lrelu(ssc[c] * v.x + ssh[c]);
    v.y = lrelu(ssc[c + 1] * v.y + ssh[c + 1]);
    z2[i] = v;
    g_zh[lz][i] = pack_bf16x2(v);
}

// ---------------- FC layer 1: chunk1 applies z3's BN on the fly ----------------
__global__ void __launch_bounds__(256) k_fc(
    const float* __restrict__ fcW1, const float* __restrict__ fcb1,
    const float* __restrict__ bng, const float* __restrict__ bnb,
    int chunk, int n)
{
    __shared__ float4 sWq[64][32];
    __shared__ float4 sx4[8][2][32];
    __shared__ float2 sb[32];
    __shared__ float  bstat[128];
    __shared__ float  ssc[64];
    __shared__ float  ssh[64];
    int tid = threadIdx.x;
    {
        const float2* wv = (const float2*)(fcW1 + chunk * 128 * 64);
        for (int i = tid; i < 2048; i += 256) {
            int k2 = i >> 5, c = i & 31;
            float2 a = wv[(2 * k2) * 32 + c];
            float2 b = wv[(2 * k2 + 1) * 32 + c];
            sWq[k2][c] = make_float4(a.x, a.y, b.x, b.y);
        }
        if (tid < 32) sb[tid] = (chunk == 0) ? ((const float2*)fcb1)[tid] : make_float2(0.f, 0.f);
        if (tid < 128) bstat[tid] = 0.f;
        if (chunk == 1 && tid < 64) {
            float inv = 1.0f / (float)n;
            float mean = g_statsA[2][tid] * inv;
            float var = g_statsA[2][64 + tid] * inv - mean * mean;
            float sc = bng[tid] * rsqrtf(var + 1e-5f);
            ssc[tid] = sc;
            ssh[tid] = bnb[tid] - sc * mean;
        }
    }
    __syncthreads();

    const float2* za = (const float2*)g_z[2 * chunk];
    const float2* zb = (const float2*)g_z[2 * chunk + 1];
    float2* u2 = (float2*)g_u;
    int w = tid >> 5, lane = tid & 31;
    float ssx = 0.f, ssy = 0.f, sqx = 0.f, sqy = 0.f;
    int gw = (blockIdx.x * 256 + tid) >> 5;
    int nw = (gridDim.x * 256) >> 5;
    float scx = 0.f, scy = 0.f, shx = 0.f, shy = 0.f;
    if (chunk == 1) {
        scx = ssc[2 * lane]; scy = ssc[2 * lane + 1];
        shx = ssh[2 * lane]; shy = ssh[2 * lane + 1];
    }

    for (int base = gw * 2; base < n; base += nw * 2) {
        int nA = base, nB = base + 1;
        bool hasB = (nB < n);
        float2 vbA = zb[nA * 32 + lane];
        if (chunk == 1) {
            vbA.x = lrelu(scx * vbA.x + shx);
            vbA.y = lrelu(scy * vbA.y + shy);
        }
        ((float2*)sx4[w][0])[lane]      = za[nA * 32 + lane];
        ((float2*)sx4[w][0])[32 + lane] = vbA;
        if (hasB) {
            float2 vbB = zb[nB * 32 + lane];
            if (chunk == 1) {
                vbB.x = lrelu(scx * vbB.x + shx);
                vbB.y = lrelu(scy * vbB.y + shy);
            }
            ((float2*)sx4[w][1])[lane]      = za[nB * 32 + lane];
            ((float2*)sx4[w][1])[32 + lane] = vbB;
        }
        __syncwarp();

        float2 uA = (chunk == 0) ? sb[lane] : u2[nA * 32 + lane];
        float2 uB = (chunk == 0) ? sb[lane] : (hasB ? u2[nB * 32 + lane] : make_float2(0.f, 0.f));
        const float4* xAv = (const float4*)sx4[w][0];
        const float4* xBv = (const float4*)sx4[w][1];
        #pragma unroll
        for (int kk = 0; kk < 32; kk++) {
            float4 m4A = xAv[kk];
            float4 m4B = xBv[kk];
            float4 w0 = sWq[2 * kk][lane];
            float4 w1 = sWq[2 * kk + 1][lane];
            uA.x = fmaf(m4A.x, w0.x, uA.x); uA.y = fmaf(m4A.x, w0.y, uA.y);
            uA.x = fmaf(m4A.y, w0.z, uA.x); uA.y = fmaf(m4A.y, w0.w, uA.y);
            uA.x = fmaf(m4A.z, w1.x, uA.x); uA.y = fmaf(m4A.z, w1.y, uA.y);
            uA.x = fmaf(m4A.w, w1.z, uA.x); uA.y = fmaf(m4A.w, w1.w, uA.y);
            uB.x = fmaf(m4B.x, w0.x, uB.x); uB.y = fmaf(m4B.x, w0.y, uB.y);
            uB.x = fmaf(m4B.y, w0.z, uB.x); uB.y = fmaf(m4B.y, w0.w, uB.y);
            uB.x = fmaf(m4B.z, w1.x, uB.x); uB.y = fmaf(m4B.z, w1.y, uB.y);
            uB.x = fmaf(m4B.w, w1.z, uB.x); uB.y = fmaf(m4B.w, w1.w, uB.y);
        }
        u2[nA * 32 + lane] = uA;
        if (chunk == 1) { ssx += uA.x; ssy += uA.y; sqx += uA.x * uA.x; sqy += uA.y * uA.y; }
        if (hasB) {
            u2[nB * 32 + lane] = uB;
            if (chunk == 1) { ssx += uB.x; ssy += uB.y; sqx += uB.x * uB.x; sqy += uB.y * uB.y; }
        }
        __syncwarp();
    }

    if (chunk == 1) {
        atomicAdd(&bstat[2 * lane], ssx);
        atomicAdd(&bstat[2 * lane + 1], ssy);
        atomicAdd(&bstat[64 + 2 * lane], sqx);
        atomicAdd(&bstat[64 + 2 * lane + 1], sqy);
        __syncthreads();
        if (tid < 128) atomicAdd(&g_statsA[3][tid], bstat[tid]);
    }
}

// ---------------- head -----------------------------------------------------
__global__ void k_head(const float* __restrict__ g, const float* __restrict__ b,
                       const float* __restrict__ fcW2, const float* __restrict__ fcb2,
                       float* __restrict__ out, int n) {
    __shared__ float ssc[64];
    __shared__ float ssh[64];
    int tid = threadIdx.x;
    if (tid < 64) {
        float inv = 1.0f / (float)n;
        float mean = g_statsA[3][tid] * inv;
        float var = g_statsA[3][64 + tid] * inv - mean * mean;
        float sc = g[tid] * rsqrtf(var + 1e-5f);
        ssc[tid] = sc;
        ssh[tid] = b[tid] - sc * mean;
    }
    __syncthreads();
    int gt = blockIdx.x * blockDim.x + tid;
    int node = gt >> 5, lane = gt & 31;
    if (node >= n) return;
    float2 u = ((const float2*)g_u)[node * 32 + lane];
    int c = 2 * lane;
    float y0 = lrelu(ssc[c] * u.x + ssh[c]);
    float y1 = lrelu(ssc[c + 1] * u.y + ssh[c + 1]);
    float p = y0 * fcW2[c] + y1 * fcW2[c + 1];
    #pragma unroll
    for (int o = 16; o > 0; o >>= 1) p += __shfl_xor_sync(0xffffffffu, p, o);
    if (lane == 0) out[node] = 1.0f / (1.0f + expf(-(p + fcb2[0])));
}

// ---------------- launch -------------------------------------------------------
extern "C" void kernel_launch(void* const* d_in, const int* in_sizes, int n_in,
                              void* d_out, int out_size) {
    const int*   node_deg = (const int*)d_in[0];
    const int*   edge_idx = (const int*)d_in[1];
    const float* embed    = (const float*)d_in[2];
    const float* eps      = (const float*)d_in[3];
    const float* W1       = (const float*)d_in[4];
    const float* b1       = (const float*)d_in[5];
    const float* W2       = (const float*)d_in[6];
    const float* b2       = (const float*)d_in[7];
    const float* bn_g     = (const float*)d_in[8];
    const float* bn_b     = (const float*)d_in[9];
    const float* fcW1     = (const float*)d_in[10];
    const float* fcb1     = (const float*)d_in[11];
    const float* fc_bn_g  = (const float*)d_in[12];
    const float* fc_bn_b  = (const float*)d_in[13];
    const float* fcW2     = (const float*)d_in[14];
    const float* fcb2     = (const float*)d_in[15];

    int n = in_sizes[0];
    int e = in_sizes[1] / 2;
    const int* src = edge_idx;
    const int* dst = edge_idx + e;

    int elemBlocks = (n * 32 + 255) / 256;
    int nb = (n + 1023) / 1024;
    const int PGRID = 592;

    bool vec4 = ((e & 3) == 0)
             && ((((unsigned long long)(size_t)src) & 15ull) == 0)
             && ((((unsigned long long)(size_t)dst) & 15ull) == 0);

    k_zero<<<(n + 255) / 256, 256>>>(n);
    if (vec4) {
        k_hist4e<<<1024, 256>>>(dst, e / 4, e, node_deg, embed, n);
    } else {
        k_hist<<<1024, 256>>>(dst, e);
        k_embed<<<elemBlocks, 256>>>(node_deg, embed, n);
    }
    k_scan1<<<nb, 1024>>>(n);
    k_scan2<<<1, 128>>>(nb);
    k_scan3<<<nb, 1024>>>(n, e);
    if (vec4) k_fill4<<<1024, 256>>>(src, dst, e / 4, e);
    else      k_fill<<<1024, 256>>>(src, dst, e);

    for (int l = 0; l < 2; l++) {
        k_layer<<<PGRID, 256>>>(W1, b1, W2, b2, eps, l, n);
        k_bnapply<<<elemBlocks, 256>>>(bn_g + l * 64, bn_b + l * 64, l + 1, n);
    }
    k_layer<<<PGRID, 256>>>(W1, b1, W2, b2, eps, 2, n);

    k_fc<<<PGRID, 256>>>(fcW1, fcb1, bn_g + 128, bn_b + 128, 0, n);
    k_fc<<<PGRID, 256>>>(fcW1, fcb1, bn_g + 128, bn_b + 128, 1, n);
    k_head<<<elemBlocks, 256>>>(fc_bn_g, fc_bn_b, fcW2, fcb2, (float*)d_out, n);
}

// round 16
// speedup vs baseline: 1.6617x; 1.0135x over previous
#include <cuda_runtime.h>
#include <cuda_bf16.h>
#include <stdint.h>
#include <math.h>

#define MAXN 100000
#define MAXE 3200000

// ---------------- scratch (static device globals) ---------------------------
__device__ int          g_cursor[MAXN];
__device__ int          g_rowptr[MAXN + 1];
__device__ int          g_col[MAXE];
__device__ int          g_bsum[256];
__device__ int          g_ticket[8];
__device__ float        g_z[4][MAXN * 64];     // fp32 master copies z0..z3 (z3 RAW pre-BN)
__device__ unsigned int g_zh[3][MAXN * 32];    // bf16x2 gather copies
__device__ float        g_u[MAXN * 64];
__device__ float        g_statsA[4][128];

__device__ __forceinline__ float lrelu(float x) { return x >= 0.f ? x : 0.01f * x; }

__device__ __forceinline__ unsigned int pack_bf16x2(float2 v) {
    __nv_bfloat162 b = __float22bfloat162_rn(v);
    return *(unsigned int*)&b;
}
__device__ __forceinline__ float bf_lo(unsigned int w) { return __int_as_float((int)(w << 16)); }
__device__ __forceinline__ float bf_hi(unsigned int w) { return __int_as_float((int)(w & 0xffff0000u)); }

// ---------------- init -------------------------------------------------------
__global__ void k_zero(int n) {
    int i = blockIdx.x * blockDim.x + threadIdx.x;
    if (i < n) g_cursor[i] = 0;
    if (i < 512) ((float*)g_statsA)[i] = 0.f;
    if (i < 8) g_ticket[i] = 0;
}

// ---------------- fused hist + embed ------------------------------------------
__global__ void k_hist4e(const int* __restrict__ dst, int e4, int e,
                         const int* __restrict__ deg, const float* __restrict__ emb, int n) {
    int stride = gridDim.x * blockDim.x;
    int t0 = blockIdx.x * blockDim.x + threadIdx.x;
    const int4* d4 = (const int4*)dst;
    for (int i = t0; i < e4; i += stride) {
        int4 d = d4[i];
        atomicAdd(&g_cursor[d.x], 1);
        atomicAdd(&g_cursor[d.y], 1);
        atomicAdd(&g_cursor[d.z], 1);
        atomicAdd(&g_cursor[d.w], 1);
    }
    for (int i = e4 * 4 + t0; i < e; i += stride)
        atomicAdd(&g_cursor[dst[i]], 1);
    int total = n * 32;
    for (int i = t0; i < total; i += stride) {
        int node = i >> 5, j = i & 31;
        float2 v = ((const float2*)emb)[deg[node] * 32 + j];
        ((float2*)g_z[0])[i] = v;
        g_zh[0][i] = pack_bf16x2(v);
    }
}

__global__ void k_hist(const int* __restrict__ dst, int e) {
    int stride = gridDim.x * blockDim.x;
    for (int i = blockIdx.x * blockDim.x + threadIdx.x; i < e; i += stride)
        atomicAdd(&g_cursor[dst[i]], 1);
}
__global__ void k_embed(const int* __restrict__ deg, const float* __restrict__ emb, int n) {
    int i = blockIdx.x * blockDim.x + threadIdx.x;
    if (i >= n * 32) return;
    int node = i >> 5, j = i & 31;
    float2 v = ((const float2*)emb)[deg[node] * 32 + j];
    ((float2*)g_z[0])[i] = v;
    g_zh[0][i] = pack_bf16x2(v);
}
__global__ void k_fill(const int* __restrict__ src, const int* __restrict__ dst, int e) {
    int stride = gridDim.x * blockDim.x;
    for (int i = blockIdx.x * blockDim.x + threadIdx.x; i < e; i += stride) {
        int p = atomicAdd(&g_cursor[dst[i]], 1);
        g_col[p] = src[i];
    }
}

__global__ void k_scan1(int n) {
    __shared__ int wsum[32];
    int tid = threadIdx.x, lane = tid & 31, w = tid >> 5;
    int i = blockIdx.x * 1024 + tid;
    int v = (i < n) ? g_cursor[i] : 0;
    int x = v;
    #pragma unroll
    for (int off = 1; off < 32; off <<= 1) {
        int t = __shfl_up_sync(0xffffffffu, x, off);
        if (lane >= off) x += t;
    }
    if (lane == 31) wsum[w] = x;
    __syncthreads();
    if (w == 0) {
        int s = wsum[lane];
        #pragma unroll
        for (int off = 1; off < 32; off <<= 1) {
            int t = __shfl_up_sync(0xffffffffu, s, off);
            if (lane >= off) s += t;
        }
        wsum[lane] = s;
    }
    __syncthreads();
    int incl = x + (w > 0 ? wsum[w - 1] : 0);
    if (i < n) g_rowptr[i] = incl - v;
    if (tid == 1023) g_bsum[blockIdx.x] = incl;
}

__global__ void k_scan2(int nb) {
    __shared__ int ws[4];
    int tid = threadIdx.x, lane = tid & 31, w = tid >> 5;
    int v = (tid < nb) ? g_bsum[tid] : 0;
    int x = v;
    #pragma unroll
    for (int off = 1; off < 32; off <<= 1) {
        int t = __shfl_up_sync(0xffffffffu, x, off);
        if (lane >= off) x += t;
    }
    if (lane == 31) ws[w] = x;
    __syncthreads();
    if (tid == 0) {
        int c = 0;
        #pragma unroll
        for (int k = 0; k < 4; k++) { int t = ws[k]; ws[k] = c; c += t; }
    }
    __syncthreads();
    if (tid < nb) g_bsum[tid] = x - v + ws[w];
}

__global__ void k_scan3(int n, int e) {
    int i = blockIdx.x * 1024 + threadIdx.x;
    if (i < n) {
        int v = g_rowptr[i] + g_bsum[blockIdx.x];
        g_rowptr[i] = v;
        g_cursor[i] = v;
    }
    if (i == 0) g_rowptr[n] = e;
}

__global__ void k_fill4(const int* __restrict__ src, const int* __restrict__ dst, int e4, int e) {
    int stride = gridDim.x * blockDim.x;
    int t0 = blockIdx.x * blockDim.x + threadIdx.x;
    const int4* s4 = (const int4*)src;
    const int4* d4 = (const int4*)dst;
    for (int i = t0; i < e4; i += stride) {
        int4 d = d4[i];
        int4 s = s4[i];
        int p0 = atomicAdd(&g_cursor[d.x], 1);
        int p1 = atomicAdd(&g_cursor[d.y], 1);
        int p2 = atomicAdd(&g_cursor[d.z], 1);
        int p3 = atomicAdd(&g_cursor[d.w], 1);
        g_col[p0] = s.x; g_col[p1] = s.y; g_col[p2] = s.z; g_col[p3] = s.w;
    }
    for (int i = e4 * 4 + t0; i < e; i += stride) {
        int p = atomicAdd(&g_cursor[dst[i]], 1);
        g_col[p] = src[i];
    }
}

// ---------------- fused GIN layer (frozen R14 form) ---------------------------
__global__ void __launch_bounds__(256) k_layer(
    const float* __restrict__ W1, const float* __restrict__ b1,
    const float* __restrict__ W2, const float* __restrict__ b2,
    const float* __restrict__ epsArr, int l, int n)
{
    __shared__ float4 sW1q[32][32];
    __shared__ float4 sW2q[32][32];
    __shared__ float2 sb1[32];
    __shared__ float2 sb2[32];
    __shared__ float4 sm4[8][2][16];
    __shared__ float4 sh4[8][2][16];
    __shared__ int    sidx[8][2][32];
    __shared__ float  bstat[128];

    int tid = threadIdx.x;
    {
        const float2* w1v = (const float2*)(W1 + l * 4096);
        const float2* w2v = (const float2*)(W2 + l * 4096);
        for (int i = tid; i < 1024; i += 256) {
            int k2 = i >> 5, c = i & 31;
            float2 a = w1v[(2 * k2) * 32 + c];
            float2 b = w1v[(2 * k2 + 1) * 32 + c];
            sW1q[k2][c] = make_float4(a.x, a.y, b.x, b.y);
            float2 a2 = w2v[(2 * k2) * 32 + c];
            float2 b2v = w2v[(2 * k2 + 1) * 32 + c];
            sW2q[k2][c] = make_float4(a2.x, a2.y, b2v.x, b2v.y);
        }
        if (tid < 32) {
            sb1[tid] = ((const float2*)(b1 + l * 64))[tid];
            sb2[tid] = ((const float2*)(b2 + l * 64))[tid];
        }
        if (tid < 128) bstat[tid] = 0.f;
    }
    __syncthreads();

    float ep = 1.0f + epsArr[l];
    const float2*       __restrict__ x2 = (const float2*)g_z[l];
    const unsigned int* __restrict__ xh = g_zh[l];
    float2* o2 = (float2*)g_z[l + 1];
    int w = tid >> 5, lane = tid & 31;
    float ssx = 0.f, ssy = 0.f, sqx = 0.f, sqy = 0.f;
    int pairs = (n + 1) / 2;

    while (true) {
        int tk;
        if (lane == 0) tk = atomicAdd(&g_ticket[l], 1);
        tk = __shfl_sync(0xffffffffu, tk, 0);
        if (tk >= pairs) break;
        int base = tk * 2;
        int nA = base, nB = base + 1;
        bool hasB = (nB < n);

        int bA = g_rowptr[nA], reA = g_rowptr[nA + 1];
        int bB = hasB ? g_rowptr[nB] : 0, reB = hasB ? g_rowptr[nB + 1] : 0;
        float2 xvA = x2[nA * 32 + lane];
        float2 xvB = hasB ? x2[nB * 32 + lane] : make_float2(0.f, 0.f);
        float aA0x = ep * xvA.x, aA0y = ep * xvA.y, aA1x = 0.f, aA1y = 0.f;
        float aB0x = ep * xvB.x, aB0y = ep * xvB.y, aB1x = 0.f, aB1y = 0.f;

        const int4* iA4 = (const int4*)sidx[w][0];
        const int4* iB4 = (const int4*)sidx[w][1];

        while (bA + 32 <= reA && bB + 32 <= reB) {
            sidx[w][0][lane] = g_col[bA + lane];
            sidx[w][1][lane] = g_col[bB + lane];
            __syncwarp();
            #pragma unroll
            for (int q = 0; q < 8; q++) {
                int4 ja = iA4[q];
                int4 jb = iB4[q];
                unsigned int wA0 = xh[ja.x * 32 + lane];
                unsigned int wA1 = xh[ja.y * 32 + lane];
                unsigned int wB0 = xh[jb.x * 32 + lane];
                unsigned int wB1 = xh[jb.y * 32 + lane];
                unsigned int wA2 = xh[ja.z * 32 + lane];
                unsigned int wA3 = xh[ja.w * 32 + lane];
                unsigned int wB2 = xh[jb.z * 32 + lane];
                unsigned int wB3 = xh[jb.w * 32 + lane];
                aA0x += bf_lo(wA0); aA0y += bf_hi(wA0);
                aA1x += bf_lo(wA1); aA1y += bf_hi(wA1);
                aB0x += bf_lo(wB0); aB0y += bf_hi(wB0);
                aB1x += bf_lo(wB1); aB1y += bf_hi(wB1);
                aA0x += bf_lo(wA2); aA0y += bf_hi(wA2);
                aA1x += bf_lo(wA3); aA1y += bf_hi(wA3);
                aB0x += bf_lo(wB2); aB0y += bf_hi(wB2);
                aB1x += bf_lo(wB3); aB1y += bf_hi(wB3);
            }
            __syncwarp();
            bA += 32; bB += 32;
        }
        while (bA + 32 <= reA) {
            sidx[w][0][lane] = g_col[bA + lane];
            __syncwarp();
            #pragma unroll
            for (int q = 0; q < 8; q++) {
                int4 ja = iA4[q];
                unsigned int w0 = xh[ja.x * 32 + lane];
                unsigned int w1 = xh[ja.y * 32 + lane];
                unsigned int w2 = xh[ja.z * 32 + lane];
                unsigned int w3 = xh[ja.w * 32 + lane];
                aA0x += bf_lo(w0); aA0y += bf_hi(w0);
                aA1x += bf_lo(w1); aA1y += bf_hi(w1);
                aA0x += bf_lo(w2); aA0y += bf_hi(w2);
                aA1x += bf_lo(w3); aA1y += bf_hi(w3);
            }
            __syncwarp();
            bA += 32;
        }
        while (bB + 32 <= reB) {
            sidx[w][1][lane] = g_col[bB + lane];
            __syncwarp();
            #pragma unroll
            for (int q = 0; q < 8; q++) {
                int4 jb = iB4[q];
                unsigned int w0 = xh[jb.x * 32 + lane];
                unsigned int w1 = xh[jb.y * 32 + lane];
                unsigned int w2 = xh[jb.z * 32 + lane];
                unsigned int w3 = xh[jb.w * 32 + lane];
                aB0x += bf_lo(w0); aB0y += bf_hi(w0);
                aB1x += bf_lo(w1); aB1y += bf_hi(w1);
                aB0x += bf_lo(w2); aB0y += bf_hi(w2);
                aB1x += bf_lo(w3); aB1y += bf_hi(w3);
            }
            __syncwarp();
            bB += 32;
        }
        {
            int remA = reA - bA, remB = reB - bB;
            if (lane < remA) sidx[w][0][lane] = g_col[bA + lane];
            if (lane < remB) sidx[w][1][lane] = g_col[bB + lane];
            __syncwarp();
            int rem = remA > remB ? remA : remB;
            for (int t = 0; t < rem; t++) {
                if (t < remA) {
                    unsigned int wv = xh[sidx[w][0][t] * 32 + lane];
                    aA0x += bf_lo(wv); aA0y += bf_hi(wv);
                }
                if (t < remB) {
                    unsigned int wv = xh[sidx[w][1][t] * 32 + lane];
                    aB0x += bf_lo(wv); aB0y += bf_hi(wv);
                }
            }
            __syncwarp();
        }
        ((float2*)sm4[w][0])[lane] = make_float2(aA0x + aA1x, aA0y + aA1y);
        ((float2*)sm4[w][1])[lane] = make_float2(aB0x + aB1x, aB0y + aB1y);
        __syncwarp();

        float2 hA = sb1[lane], hB = sb1[lane];
        const float4* mAv = (const float4*)sm4[w][0];
        const float4* mBv = (const float4*)sm4[w][1];
        #pragma unroll
        for (int kk = 0; kk < 16; kk++) {
            float4 m4A = mAv[kk];
            float4 m4B = mBv[kk];
            float4 w0 = sW1q[2 * kk][lane];
            float4 w1 = sW1q[2 * kk + 1][lane];
            hA.x = fmaf(m4A.x, w0.x, hA.x); hA.y = fmaf(m4A.x, w0.y, hA.y);
            hA.x = fmaf(m4A.y, w0.z, hA.x); hA.y = fmaf(m4A.y, w0.w, hA.y);
            hA.x = fmaf(m4A.z, w1.x, hA.x); hA.y = fmaf(m4A.z, w1.y, hA.y);
            hA.x = fmaf(m4A.w, w1.z, hA.x); hA.y = fmaf(m4A.w, w1.w, hA.y);
            hB.x = fmaf(m4B.x, w0.x, hB.x); hB.y = fmaf(m4B.x, w0.y, hB.y);
            hB.x = fmaf(m4B.y, w0.z, hB.x); hB.y = fmaf(m4B.y, w0.w, hB.y);
            hB.x = fmaf(m4B.z, w1.x, hB.x); hB.y = fmaf(m4B.z, w1.y, hB.y);
            hB.x = fmaf(m4B.w, w1.z, hB.x); hB.y = fmaf(m4B.w, w1.w, hB.y);
        }
        hA.x = lrelu(hA.x); hA.y = lrelu(hA.y);
        hB.x = lrelu(hB.x); hB.y = lrelu(hB.y);
        ((float2*)sh4[w][0])[lane] = hA;
        ((float2*)sh4[w][1])[lane] = hB;
        __syncwarp();

        float2 oA = sb2[lane], oB = sb2[lane];
        const float4* hAv = (const float4*)sh4[w][0];
        const float4* hBv = (const float4*)sh4[w][1];
        #pragma unroll
        for (int kk = 0; kk < 16; kk++) {
            float4 m4A = hAv[kk];
            float4 m4B = hBv[kk];
            float4 w0 = sW2q[2 * kk][lane];
            float4 w1 = sW2q[2 * kk + 1][lane];
            oA.x = fmaf(m4A.x, w0.x, oA.x); oA.y = fmaf(m4A.x, w0.y, oA.y);
            oA.x = fmaf(m4A.y, w0.z, oA.x); oA.y = fmaf(m4A.y, w0.w, oA.y);
            oA.x = fmaf(m4A.z, w1.x, oA.x); oA.y = fmaf(m4A.z, w1.y, oA.y);
            oA.x = fmaf(m4A.w, w1.z, oA.x); oA.y = fmaf(m4A.w, w1.w, oA.y);
            oB.x = fmaf(m4B.x, w0.x, oB.x); oB.y = fmaf(m4B.x, w0.y, oB.y);
            oB.x = fmaf(m4B.y, w0.z, oB.x); oB.y = fmaf(m4B.y, w0.w, oB.y);
            oB.x = fmaf(m4B.z, w1.x, oB.x); oB.y = fmaf(m4B.z, w1.y, oB.y);
            oB.x = fmaf(m4B.w, w1.z, oB.x); oB.y = fmaf(m4B.w, w1.w, oB.y);
        }
        o2[nA * 32 + lane] = oA;
        ssx += oA.x; ssy += oA.y; sqx += oA.x * oA.x; sqy += oA.y * oA.y;
        if (hasB) {
            o2[nB * 32 + lane] = oB;
            ssx += oB.x; ssy += oB.y; sqx += oB.x * oB.x; sqy += oB.y * oB.y;
        }
        __syncwarp();
    }

    atomicAdd(&bstat[2 * lane], ssx);
    atomicAdd(&bstat[2 * lane + 1], ssy);
    atomicAdd(&bstat[64 + 2 * lane], sqx);
    atomicAdd(&bstat[64 + 2 * lane + 1], sqy);
    __syncthreads();
    if (tid < 128) atomicAdd(&g_statsA[l][tid], bstat[tid]);
}

// ---------------- BN + leaky for z1/z2 ----------------------------------------
__global__ void k_bnapply(const float* __restrict__ g, const float* __restrict__ b,
                          int lz, int n) {
    __shared__ float ssc[64];
    __shared__ float ssh[64];
    int tid = threadIdx.x;
    int slot = lz - 1;
    if (tid < 64) {
        float inv = 1.0f / (float)n;
        float mean = g_statsA[slot][tid] * inv;
        float var = g_statsA[slot][64 + tid] * inv - mean * mean;
        float sc = g[tid] * rsqrtf(var + 1e-5f);
        ssc[tid] = sc;
        ssh[tid] = b[tid] - sc * mean;
    }
    __syncthreads();
    int i = blockIdx.x * blockDim.x + tid;
    if (i >= n * 32) return;
    int c = (i & 31) * 2;
    float2* z2 = (float2*)g_z[lz];
    float2 v = z2[i];
    v.x = lrelu(ssc[c] * v.x + ssh[c]);
    v.y = lrelu(ssc[c + 1] * v.y + ssh[c + 1]);
    z2[i] = v;
    g_zh[lz][i] = pack_bf16x2(v);
}

// ---------------- merged FC layer 1: full 256x64 GEMV, one pass ---------------
// dynamic smem layout: [0, 64KB) = sWq (128 k2-rows x 32 lanes, float4)
//                      [64KB, 80KB) = sx4 (8 warps x 2 nodes x 64 float4)
__global__ void __launch_bounds__(256) k_fcall(
    const float* __restrict__ fcW1, const float* __restrict__ fcb1,
    const float* __restrict__ bng, const float* __restrict__ bnb, int n)
{
    extern __shared__ float4 dyn[];
    float4* sWq = dyn;                      // [128][32]
    float4* sx4 = dyn + 4096;               // [8][2][64]
    __shared__ float2 sb[32];
    __shared__ float  bstat[128];
    __shared__ float  ssc[64];
    __shared__ float  ssh[64];
    int tid = threadIdx.x;
    {
        const float2* wv = (const float2*)fcW1;   // [256][64] -> float2 [256][32]
        for (int i = tid; i < 4096; i += 256) {
            int k2 = i >> 5, c = i & 31;
            float2 a = wv[(2 * k2) * 32 + c];
            float2 b = wv[(2 * k2 + 1) * 32 + c];
            sWq[k2 * 32 + c] = make_float4(a.x, a.y, b.x, b.y);
        }
        if (tid < 32) sb[tid] = ((const float2*)fcb1)[tid];
        if (tid < 128) bstat[tid] = 0.f;
        if (tid < 64) {
            float inv = 1.0f / (float)n;
            float mean = g_statsA[2][tid] * inv;
            float var = g_statsA[2][64 + tid] * inv - mean * mean;
            float sc = bng[tid] * rsqrtf(var + 1e-5f);
            ssc[tid] = sc;
            ssh[tid] = bnb[tid] - sc * mean;
        }
    }
    __syncthreads();

    const float2* z0 = (const float2*)g_z[0];
    const float2* z1 = (const float2*)g_z[1];
    const float2* zz2 = (const float2*)g_z[2];
    const float2* z3 = (const float2*)g_z[3];
    float2* u2 = (float2*)g_u;
    int w = tid >> 5, lane = tid & 31;
    float ssx = 0.f, ssy = 0.f, sqx = 0.f, sqy = 0.f;
    int gw = (blockIdx.x * 256 + tid) >> 5;
    int nw = (gridDim.x * 256) >> 5;
    float scx = ssc[2 * lane], scy = ssc[2 * lane + 1];
    float shx = ssh[2 * lane], shy = ssh[2 * lane + 1];

    float2* sxA = (float2*)(sx4 + (w * 2 + 0) * 64);
    float2* sxB = (float2*)(sx4 + (w * 2 + 1) * 64);

    for (int base = gw * 2; base < n; base += nw * 2) {
        int nA = base, nB = base + 1;
        bool hasB = (nB < n);
        {
            float2 v3 = z3[nA * 32 + lane];
            v3.x = lrelu(scx * v3.x + shx);
            v3.y = lrelu(scy * v3.y + shy);
            sxA[lane]      = z0[nA * 32 + lane];
            sxA[32 + lane] = z1[nA * 32 + lane];
            sxA[64 + lane] = zz2[nA * 32 + lane];
            sxA[96 + lane] = v3;
        }
        if (hasB) {
            float2 v3 = z3[nB * 32 + lane];
            v3.x = lrelu(scx * v3.x + shx);
            v3.y = lrelu(scy * v3.y + shy);
            sxB[lane]      = z0[nB * 32 + lane];
            sxB[32 + lane] = z1[nB * 32 + lane];
            sxB[64 + lane] = zz2[nB * 32 + lane];
            sxB[96 + lane] = v3;
        }
        __syncwarp();

        float2 uA = sb[lane], uB = sb[lane];
        const float4* xAv = (const float4*)sxA;
        const float4* xBv = (const float4*)sxB;
        #pragma unroll
        for (int kk = 0; kk < 64; kk++) {
            float4 m4A = xAv[kk];
            float4 m4B = xBv[kk];
            float4 w0 = sWq[(2 * kk) * 32 + lane];
            float4 w1 = sWq[(2 * kk + 1) * 32 + lane];
            uA.x = fmaf(m4A.x, w0.x, uA.x); uA.y = fmaf(m4A.x, w0.y, uA.y);
            uA.x = fmaf(m4A.y, w0.z, uA.x); uA.y = fmaf(m4A.y, w0.w, uA.y);
            uA.x = fmaf(m4A.z, w1.x, uA.x); uA.y = fmaf(m4A.z, w1.y, uA.y);
            uA.x = fmaf(m4A.w, w1.z, uA.x); uA.y = fmaf(m4A.w, w1.w, uA.y);
            uB.x = fmaf(m4B.x, w0.x, uB.x); uB.y = fmaf(m4B.x, w0.y, uB.y);
            uB.x = fmaf(m4B.y, w0.z, uB.x); uB.y = fmaf(m4B.y, w0.w, uB.y);
            uB.x = fmaf(m4B.z, w1.x, uB.x); uB.y = fmaf(m4B.z, w1.y, uB.y);
            uB.x = fmaf(m4B.w, w1.z, uB.x); uB.y = fmaf(m4B.w, w1.w, uB.y);
        }
        u2[nA * 32 + lane] = uA;
        ssx += uA.x; ssy += uA.y; sqx += uA.x * uA.x; sqy += uA.y * uA.y;
        if (hasB) {
            u2[nB * 32 + lane] = uB;
            ssx += uB.x; ssy += uB.y; sqx += uB.x * uB.x; sqy += uB.y * uB.y;
        }
        __syncwarp();
    }

    atomicAdd(&bstat[2 * lane], ssx);
    atomicAdd(&bstat[2 * lane + 1], ssy);
    atomicAdd(&bstat[64 + 2 * lane], sqx);
    atomicAdd(&bstat[64 + 2 * lane + 1], sqy);
    __syncthreads();
    if (tid < 128) atomicAdd(&g_statsA[3][tid], bstat[tid]);
}

// ---------------- head --------------------------------------------------------
__global__ void k_head(const float* __restrict__ g, const float* __restrict__ b,
                       const float* __restrict__ fcW2, const float* __restrict__ fcb2,
                       float* __restrict__ out, int n) {
    __shared__ float ssc[64];
    __shared__ float ssh[64];
    int tid = threadIdx.x;
    if (tid < 64) {
        float inv = 1.0f / (float)n;
        float mean = g_statsA[3][tid] * inv;
        float var = g_statsA[3][64 + tid] * inv - mean * mean;
        float sc = g[tid] * rsqrtf(var + 1e-5f);
        ssc[tid] = sc;
        ssh[tid] = b[tid] - sc * mean;
    }
    __syncthreads();
    int gt = blockIdx.x * blockDim.x + tid;
    int node = gt >> 5, lane = gt & 31;
    if (node >= n) return;
    float2 u = ((const float2*)g_u)[node * 32 + lane];
    int c = 2 * lane;
    float y0 = lrelu(ssc[c] * u.x + ssh[c]);
    float y1 = lrelu(ssc[c + 1] * u.y + ssh[c + 1]);
    float p = y0 * fcW2[c] + y1 * fcW2[c + 1];
    #pragma unroll
    for (int o = 16; o > 0; o >>= 1) p += __shfl_xor_sync(0xffffffffu, p, o);
    if (lane == 0) out[node] = 1.0f / (1.0f + expf(-(p + fcb2[0])));
}

// ---------------- launch -------------------------------------------------------
extern "C" void kernel_launch(void* const* d_in, const int* in_sizes, int n_in,
                              void* d_out, int out_size) {
    const int*   node_deg = (const int*)d_in[0];
    const int*   edge_idx = (const int*)d_in[1];
    const float* embed    = (const float*)d_in[2];
    const float* eps      = (const float*)d_in[3];
    const float* W1       = (const float*)d_in[4];
    const float* b1       = (const float*)d_in[5];
    const float* W2       = (const float*)d_in[6];
    const float* b2       = (const float*)d_in[7];
    const float* bn_g     = (const float*)d_in[8];
    const float* bn_b     = (const float*)d_in[9];
    const float* fcW1     = (const float*)d_in[10];
    const float* fcb1     = (const float*)d_in[11];
    const float* fc_bn_g  = (const float*)d_in[12];
    const float* fc_bn_b  = (const float*)d_in[13];
    const float* fcW2     = (const float*)d_in[14];
    const float* fcb2     = (const float*)d_in[15];

    int n = in_sizes[0];
    int e = in_sizes[1] / 2;
    const int* src = edge_idx;
    const int* dst = edge_idx + e;

    int elemBlocks = (n * 32 + 255) / 256;
    int nb = (n + 1023) / 1024;
    const int PGRID = 592;
    const int FCSMEM = 81920;   // 64KB weights + 16KB staging
    const int FCGRID = 296;     // 148 SMs x 2 blocks at ~82KB smem

    static bool attrSet = false;
    if (!attrSet) {
        cudaFuncSetAttribute(k_fcall, cudaFuncAttributeMaxDynamicSharedMemorySize, FCSMEM);
        attrSet = true;
    }

    bool vec4 = ((e & 3) == 0)
             && ((((unsigned long long)(size_t)src) & 15ull) == 0)
             && ((((unsigned long long)(size_t)dst) & 15ull) == 0);

    k_zero<<<(n + 255) / 256, 256>>>(n);
    if (vec4) {
        k_hist4e<<<1024, 256>>>(dst, e / 4, e, node_deg, embed, n);
    } else {
        k_hist<<<1024, 256>>>(dst, e);
        k_embed<<<elemBlocks, 256>>>(node_deg, embed, n);
    }
    k_scan1<<<nb, 1024>>>(n);
    k_scan2<<<1, 128>>>(nb);
    k_scan3<<<nb, 1024>>>(n, e);
    if (vec4) k_fill4<<<1024, 256>>>(src, dst, e / 4, e);
    else      k_fill<<<1024, 256>>>(src, dst, e);

    for (int l = 0; l < 2; l++) {
        k_layer<<<PGRID, 256>>>(W1, b1, W2, b2, eps, l, n);
        k_bnapply<<<elemBlocks, 256>>>(bn_g + l * 64, bn_b + l * 64, l + 1, n);
    }
    k_layer<<<PGRID, 256>>>(W1, b1, W2, b2, eps, 2, n);

    k_fcall<<<FCGRID, 256, FCSMEM>>>(fcW1, fcb1, bn_g + 128, bn_b + 128, n);
    k_head<<<elemBlocks, 256>>>(fc_bn_g, fc_bn_b, fcW2, fcb2, (float*)d_out, n);
}